// round 2
// baseline (speedup 1.0000x reference)
#include <cuda_runtime.h>
#include <cstdint>

#define DEVI __device__ __forceinline__

constexpr int B_  = 2;
constexpr int L_  = 4096;
constexpr int D_  = 512;
constexpr int H_  = 8;
constexpr int HD_ = 64;
constexpr int M_  = B_ * L_;   // 8192

// scratch: __device__ globals (allocation-free rule)
__device__ float g_q[B_*H_*L_*HD_];
__device__ float g_k[B_*H_*L_*HD_];
__device__ float g_v[B_*H_*L_*HD_];
__device__ float g_ctx[M_*D_];

DEVI uint32_t f2tf32(float x){ uint32_t r; asm("cvt.rna.tf32.f32 %0, %1;":"=r"(r):"f"(x)); return r; }

DEVI void mma16n8k8(float* c, const uint32_t* a, const uint32_t* b){
  asm volatile("mma.sync.aligned.m16n8k8.row.col.f32.tf32.tf32.f32 "
    "{%0,%1,%2,%3},{%4,%5,%6,%7},{%8,%9},{%0,%1,%2,%3};\n"
    : "+f"(c[0]),"+f"(c[1]),"+f"(c[2]),"+f"(c[3])
    : "r"(a[0]),"r"(a[1]),"r"(a[2]),"r"(a[3]),"r"(b[0]),"r"(b[1]));
}

DEVI void cpa16(void* s, const void* g){
  uint32_t sa = (uint32_t)__cvta_generic_to_shared(s);
  asm volatile("cp.async.cg.shared.global [%0], [%1], 16;\n"::"r"(sa),"l"(g));
}
DEVI void cpa_commit(){ asm volatile("cp.async.commit_group;\n"); }
template<int N> DEVI void cpa_wait(){ asm volatile("cp.async.wait_group %0;\n"::"n"(N)); }

// ---------------------------------------------------------------------------
// TF32 GEMM: C[M,512] = A[M,512] @ W[512,512] + bias
// mode 0/4: plain output (mode 4: A = g_ctx). mode 1/2/3: scatter to g_q/g_k/g_v
// ---------------------------------------------------------------------------
constexpr int BM = 128, BN = 128, BK = 32;
constexpr int AST = BK + 4;    // 36
constexpr int BST = BN + 8;    // 136
constexpr int GEMM_SMEM = (2*BM*AST + 2*BK*BST) * 4;

__global__ void __launch_bounds__(256,2) gemm_tf32(
  const float* __restrict__ Ain, const float* __restrict__ W,
  const float* __restrict__ bias, float* __restrict__ Cplain, int mode)
{
  extern __shared__ float sm[];
  float* As = sm;                  // [2][BM][AST]
  float* Bs = sm + 2*BM*AST;       // [2][BK][BST]
  const float* A = (mode==4) ? g_ctx : Ain;
  float* C = (mode==0 || mode==4) ? Cplain : (mode==1 ? g_q : (mode==2 ? g_k : g_v));

  int tid = threadIdx.x;
  int m0 = blockIdx.y*BM, n0 = blockIdx.x*BN;
  int w = tid>>5, lane = tid&31, g = lane>>2, tg = lane&3;
  int wm = (w>>1)*32, wn = (w&1)*64;

  const float* gA = A + (size_t)m0*D_;
  const float* gB = W + n0;

  float acc[2][8][4];
  #pragma unroll
  for(int i=0;i<2;i++)
    #pragma unroll
    for(int j=0;j<8;j++)
      #pragma unroll
      for(int k=0;k<4;k++) acc[i][j][k]=0.f;

  auto load_tiles = [&](int buf, int kt){
    #pragma unroll
    for(int j=0;j<4;j++){                       // A: 128x32
      int idx = tid + j*256;
      int r = idx>>3, c4 = idx&7;
      cpa16(&As[buf*BM*AST + r*AST + c4*4], gA + (size_t)r*D_ + kt*BK + c4*4);
    }
    #pragma unroll
    for(int j=0;j<4;j++){                       // B: 32x128
      int idx = tid + j*256;
      int r = idx>>5, c4 = idx&31;
      cpa16(&Bs[buf*BK*BST + r*BST + c4*4], gB + (size_t)(kt*BK + r)*D_ + c4*4);
    }
  };

  load_tiles(0,0); cpa_commit();

  #pragma unroll 1
  for(int kt=0; kt<D_/BK; kt++){
    if(kt+1 < D_/BK){ load_tiles((kt+1)&1, kt+1); cpa_commit(); cpa_wait<1>(); }
    else            { cpa_wait<0>(); }
    __syncthreads();
    const float* as = As + (kt&1)*BM*AST;
    const float* bs = Bs + (kt&1)*BK*BST;
    #pragma unroll
    for(int kk=0; kk<BK; kk+=8){
      uint32_t af[2][4], bf[8][2];
      #pragma unroll
      for(int im=0;im<2;im++){
        int rb = wm + im*16;
        af[im][0] = f2tf32(as[(rb+g  )*AST + kk+tg  ]);
        af[im][1] = f2tf32(as[(rb+g+8)*AST + kk+tg  ]);
        af[im][2] = f2tf32(as[(rb+g  )*AST + kk+tg+4]);
        af[im][3] = f2tf32(as[(rb+g+8)*AST + kk+tg+4]);
      }
      #pragma unroll
      for(int in=0;in<8;in++){
        int cb = wn + in*8 + g;
        bf[in][0] = f2tf32(bs[(kk+tg  )*BST + cb]);
        bf[in][1] = f2tf32(bs[(kk+tg+4)*BST + cb]);
      }
      #pragma unroll
      for(int im=0;im<2;im++)
        #pragma unroll
        for(int in=0;in<8;in++)
          mma16n8k8(acc[im][in], af[im], bf[in]);
    }
    __syncthreads();
  }

  #pragma unroll
  for(int im=0;im<2;im++){
    int r0 = m0 + wm + im*16 + g;
    #pragma unroll
    for(int in=0;in<8;in++){
      int col = n0 + wn + in*8 + tg*2;
      float bx = bias[col], by = bias[col+1];
      float2 v0 = make_float2(acc[im][in][0]+bx, acc[im][in][1]+by);
      float2 v1 = make_float2(acc[im][in][2]+bx, acc[im][in][3]+by);
      if(mode==0 || mode==4){
        *(float2*)(Cplain + (size_t)r0*D_ + col)     = v0;
        *(float2*)(Cplain + (size_t)(r0+8)*D_ + col) = v1;
      } else {
        int h = col>>6, d = col&63;
        int r8 = r0 + 8;
        size_t i0 = ((size_t)((r0>>12)*H_ + h)*L_ + (r0&4095))*HD_ + d;
        size_t i1 = ((size_t)((r8>>12)*H_ + h)*L_ + (r8&4095))*HD_ + d;
        *(float2*)(C + i0) = v0;
        *(float2*)(C + i1) = v1;
      }
    }
  }
}

// ---------------------------------------------------------------------------
// Flash attention: 1 CTA per (b*h, 128 q rows); 64-key tiles double-buffered
// ---------------------------------------------------------------------------
constexpr int FM = 128, FN = 64;
constexpr int QST = HD_ + 4;   // 68
constexpr int KST = HD_ + 4;   // 68
constexpr int VST = HD_ + 8;   // 72
constexpr int Q_FLOATS = FM*QST;
constexpr int K_FLOATS = FN*KST;
constexpr int V_FLOATS = FN*VST;
constexpr int FLASH_SMEM = (Q_FLOATS + 2*K_FLOATS + 2*V_FLOATS)*4 + 2*FN*4;

__global__ void __launch_bounds__(256) flash_attn(const int* __restrict__ mask)
{
  extern __shared__ float sm[];
  float* Qs = sm;
  float* Ks = sm + Q_FLOATS;
  float* Vs = Ks + 2*K_FLOATS;
  int*   Ms = (int*)(Vs + 2*V_FLOATS);

  int tid = threadIdx.x, w = tid>>5, lane = tid&31, g = lane>>2, tg = lane&3;
  int bh = blockIdx.y;
  int b  = bh >> 3;
  int q0 = blockIdx.x * FM;

  const float* Qg = g_q + (size_t)bh*L_*HD_ + (size_t)q0*HD_;
  const float* Kg = g_k + (size_t)bh*L_*HD_;
  const float* Vg = g_v + (size_t)bh*L_*HD_;
  const int*   mg = mask + b*L_;

  #pragma unroll
  for(int j=0;j<8;j++){                          // Q tile 128x64
    int idx = tid + j*256;
    int r = idx>>4, c4 = idx&15;
    cpa16(&Qs[r*QST + c4*4], Qg + (size_t)r*HD_ + c4*4);
  }
  cpa_commit();

  auto loadKV = [&](int buf, int it){
    const float* kg = Kg + (size_t)it*FN*HD_;
    const float* vg = Vg + (size_t)it*FN*HD_;
    #pragma unroll
    for(int j=0;j<4;j++){
      int idx = tid + j*256;
      int r = idx>>4, c4 = idx&15;
      cpa16(&Ks[buf*K_FLOATS + r*KST + c4*4], kg + (size_t)r*HD_ + c4*4);
    }
    #pragma unroll
    for(int j=0;j<4;j++){
      int idx = tid + j*256;
      int r = idx>>4, c4 = idx&15;
      cpa16(&Vs[buf*V_FLOATS + r*VST + c4*4], vg + (size_t)r*HD_ + c4*4);
    }
    if(tid < 16) cpa16(&Ms[buf*FN + tid*4], mg + it*FN + tid*4);
  };

  loadKV(0,0); cpa_commit();

  float o[8][4];
  #pragma unroll
  for(int i=0;i<8;i++)
    #pragma unroll
    for(int j=0;j<4;j++) o[i][j]=0.f;
  float mo0=-1e30f, mo1=-1e30f, lo0=0.f, lo1=0.f;

  #pragma unroll 1
  for(int it=0; it<L_/FN; it++){
    int buf = it&1;
    if(it+1 < L_/FN){ loadKV(buf^1, it+1); cpa_commit(); cpa_wait<1>(); }
    else            { cpa_wait<0>(); }
    __syncthreads();

    const float* ks = Ks + buf*K_FLOATS;
    const float* vs = Vs + buf*V_FLOATS;
    const int*   ms = Ms + buf*FN;

    // S = Q @ K^T (per warp: 16 q-rows x 64 keys)
    float s[8][4];
    #pragma unroll
    for(int i=0;i<8;i++)
      #pragma unroll
      for(int j=0;j<4;j++) s[i][j]=0.f;

    #pragma unroll
    for(int kk=0; kk<HD_; kk+=8){
      uint32_t af[4];
      int rb = w*16;
      af[0] = f2tf32(Qs[(rb+g  )*QST + kk+tg  ]);
      af[1] = f2tf32(Qs[(rb+g+8)*QST + kk+tg  ]);
      af[2] = f2tf32(Qs[(rb+g  )*QST + kk+tg+4]);
      af[3] = f2tf32(Qs[(rb+g+8)*QST + kk+tg+4]);
      #pragma unroll
      for(int in=0;in<8;in++){
        uint32_t bf[2];
        bf[0] = f2tf32(ks[(in*8+g)*KST + kk+tg  ]);
        bf[1] = f2tf32(ks[(in*8+g)*KST + kk+tg+4]);
        mma16n8k8(s[in], af, bf);
      }
    }

    const float scale = 0.125f;   // 1/sqrt(64)
    #pragma unroll
    for(int in=0;in<8;in++){
      int c0 = in*8 + tg*2;
      bool ok0 = ms[c0]!=0, ok1 = ms[c0+1]!=0;
      s[in][0] = ok0 ? s[in][0]*scale : -1e30f;
      s[in][1] = ok1 ? s[in][1]*scale : -1e30f;
      s[in][2] = ok0 ? s[in][2]*scale : -1e30f;
      s[in][3] = ok1 ? s[in][3]*scale : -1e30f;
    }

    // online softmax; rows (w*16+g) and (+8) live within one quad
    float mx0=-1e30f, mx1=-1e30f;
    #pragma unroll
    for(int in=0;in<8;in++){
      mx0 = fmaxf(mx0, fmaxf(s[in][0], s[in][1]));
      mx1 = fmaxf(mx1, fmaxf(s[in][2], s[in][3]));
    }
    mx0 = fmaxf(mx0, __shfl_xor_sync(0xffffffffu, mx0, 1));
    mx0 = fmaxf(mx0, __shfl_xor_sync(0xffffffffu, mx0, 2));
    mx1 = fmaxf(mx1, __shfl_xor_sync(0xffffffffu, mx1, 1));
    mx1 = fmaxf(mx1, __shfl_xor_sync(0xffffffffu, mx1, 2));

    float mn0 = fmaxf(mo0, mx0), mn1 = fmaxf(mo1, mx1);
    float sc0 = __expf(mo0 - mn0), sc1 = __expf(mo1 - mn1);

    float rs0=0.f, rs1=0.f;
    #pragma unroll
    for(int in=0;in<8;in++){
      s[in][0] = __expf(s[in][0]-mn0); rs0 += s[in][0];
      s[in][1] = __expf(s[in][1]-mn0); rs0 += s[in][1];
      s[in][2] = __expf(s[in][2]-mn1); rs1 += s[in][2];
      s[in][3] = __expf(s[in][3]-mn1); rs1 += s[in][3];
    }
    rs0 += __shfl_xor_sync(0xffffffffu, rs0, 1);
    rs0 += __shfl_xor_sync(0xffffffffu, rs0, 2);
    rs1 += __shfl_xor_sync(0xffffffffu, rs1, 1);
    rs1 += __shfl_xor_sync(0xffffffffu, rs1, 2);

    lo0 = lo0*sc0 + rs0;
    lo1 = lo1*sc1 + rs1;
    mo0 = mn0; mo1 = mn1;

    #pragma unroll
    for(int in=0;in<8;in++){
      o[in][0]*=sc0; o[in][1]*=sc0; o[in][2]*=sc1; o[in][3]*=sc1;
    }

    // O += P @ V ; P C-frag -> A-frag via width-4 shuffles
    #pragma unroll
    for(int kb=0;kb<8;kb++){
      int src  = tg>>1;
      int src2 = src + 2;
      float x0 = __shfl_sync(0xffffffffu, s[kb][0], src , 4);
      float x1 = __shfl_sync(0xffffffffu, s[kb][1], src , 4);
      float x2 = __shfl_sync(0xffffffffu, s[kb][2], src , 4);
      float x3 = __shfl_sync(0xffffffffu, s[kb][3], src , 4);
      float y0 = __shfl_sync(0xffffffffu, s[kb][0], src2, 4);
      float y1 = __shfl_sync(0xffffffffu, s[kb][1], src2, 4);
      float y2 = __shfl_sync(0xffffffffu, s[kb][2], src2, 4);
      float y3 = __shfl_sync(0xffffffffu, s[kb][3], src2, 4);
      bool odd = (tg&1)!=0;
      uint32_t af[4];
      af[0] = f2tf32(odd ? x1 : x0);
      af[1] = f2tf32(odd ? x3 : x2);
      af[2] = f2tf32(odd ? y1 : y0);
      af[3] = f2tf32(odd ? y3 : y2);
      #pragma unroll
      for(int in=0;in<8;in++){
        uint32_t bf[2];
        bf[0] = f2tf32(vs[(kb*8+tg  )*VST + in*8+g]);
        bf[1] = f2tf32(vs[(kb*8+tg+4)*VST + in*8+g]);
        mma16n8k8(o[in], af, bf);
      }
    }
    __syncthreads();
  }

  float inv0 = 1.f/lo0, inv1 = 1.f/lo1;
  int r0 = q0 + w*16 + g;
  float* op0 = g_ctx + (size_t)(b*L_ + r0    )*D_ + (bh&7)*HD_;
  float* op1 = g_ctx + (size_t)(b*L_ + r0 + 8)*D_ + (bh&7)*HD_;
  #pragma unroll
  for(int in=0;in<8;in++){
    int d = in*8 + tg*2;
    *(float2*)(op0 + d) = make_float2(o[in][0]*inv0, o[in][1]*inv0);
    *(float2*)(op1 + d) = make_float2(o[in][2]*inv1, o[in][3]*inv1);
  }
}

// ---------------------------------------------------------------------------
extern "C" void kernel_launch(void* const* d_in, const int* in_sizes, int n_in,
                              void* d_out, int out_size)
{
  (void)in_sizes; (void)n_in; (void)out_size;
  const float* query = (const float*)d_in[0];
  const float* key   = (const float*)d_in[1];
  const float* value = (const float*)d_in[2];
  const int*   mask  = (const int*)d_in[3];
  const float* Wq = (const float*)d_in[4];
  const float* bq = (const float*)d_in[5];
  const float* Wk = (const float*)d_in[6];
  const float* bk = (const float*)d_in[7];
  const float* Wv = (const float*)d_in[8];
  const float* bv = (const float*)d_in[9];
  const float* Wo = (const float*)d_in[10];
  const float* bo = (const float*)d_in[11];
  float* out = (float*)d_out;

  static bool attr_done = false;
  if(!attr_done){
    cudaFuncSetAttribute(gemm_tf32,  cudaFuncAttributeMaxDynamicSharedMemorySize, GEMM_SMEM);
    cudaFuncSetAttribute(flash_attn, cudaFuncAttributeMaxDynamicSharedMemorySize, FLASH_SMEM);
    attr_done = true;
  }

  dim3 gg(D_/BN, M_/BM);            // (4, 64)
  gemm_tf32<<<gg, 256, GEMM_SMEM>>>(query, Wq, bq, nullptr, 1);
  gemm_tf32<<<gg, 256, GEMM_SMEM>>>(key,   Wk, bk, nullptr, 2);
  gemm_tf32<<<gg, 256, GEMM_SMEM>>>(value, Wv, bv, nullptr, 3);

  dim3 fg(L_/FM, B_*H_);            // (32, 16)
  flash_attn<<<fg, 256, FLASH_SMEM>>>(mask);

  gemm_tf32<<<gg, 256, GEMM_SMEM>>>(nullptr, Wo, bo, out, 4);
}

// round 3
// speedup vs baseline: 1.1437x; 1.1437x over previous
#include <cuda_runtime.h>
#include <cstdint>

#define DEVI __device__ __forceinline__

constexpr int B_  = 2;
constexpr int L_  = 4096;
constexpr int D_  = 512;
constexpr int H_  = 8;
constexpr int HD_ = 64;
constexpr int M_  = B_ * L_;   // 8192

// scratch: __device__ globals (allocation-free rule)
__device__ float g_q[B_*H_*L_*HD_];
__device__ float g_k[B_*H_*L_*HD_];
__device__ float g_v[B_*H_*L_*HD_];
__device__ float g_ctx[M_*D_];

DEVI uint32_t f2tf32(float x){ uint32_t r; asm("cvt.rna.tf32.f32 %0, %1;":"=r"(r):"f"(x)); return r; }
DEVI float    rtf32(float x){ return __uint_as_float(f2tf32(x)); }

DEVI void mma16n8k8(float* c, const uint32_t* a, const uint32_t* b){
  asm volatile("mma.sync.aligned.m16n8k8.row.col.f32.tf32.tf32.f32 "
    "{%0,%1,%2,%3},{%4,%5,%6,%7},{%8,%9},{%0,%1,%2,%3};\n"
    : "+f"(c[0]),"+f"(c[1]),"+f"(c[2]),"+f"(c[3])
    : "r"(a[0]),"r"(a[1]),"r"(a[2]),"r"(a[3]),"r"(b[0]),"r"(b[1]));
}

DEVI void cpa16(void* s, const void* g){
  uint32_t sa = (uint32_t)__cvta_generic_to_shared(s);
  asm volatile("cp.async.cg.shared.global [%0], [%1], 16;\n"::"r"(sa),"l"(g));
}
DEVI void cpa_commit(){ asm volatile("cp.async.commit_group;\n"); }
template<int N> DEVI void cpa_wait(){ asm volatile("cp.async.wait_group %0;\n"::"n"(N)); }

// ---------------------------------------------------------------------------
// TF32 GEMM: C[M,512] = A[M,512] @ W[512,512] + bias
// mode 0/4: plain output (mode 4: A = g_ctx). mode 1/2/3: scatter TF32-rounded
// values to g_q/g_k/g_v so the flash kernel can skip all cvt in its hot loop.
// ---------------------------------------------------------------------------
constexpr int BM = 128, BN = 128, BK = 32;
constexpr int AST = BK + 4;    // 36
constexpr int BST = BN + 8;    // 136
constexpr int GEMM_SMEM = (2*BM*AST + 2*BK*BST) * 4;

__global__ void __launch_bounds__(256,2) gemm_tf32(
  const float* __restrict__ Ain, const float* __restrict__ W,
  const float* __restrict__ bias, float* __restrict__ Cplain, int mode)
{
  extern __shared__ float sm[];
  float* As = sm;                  // [2][BM][AST]
  float* Bs = sm + 2*BM*AST;       // [2][BK][BST]
  const float* A = (mode==4) ? g_ctx : Ain;
  float* C = (mode==0 || mode==4) ? Cplain : (mode==1 ? g_q : (mode==2 ? g_k : g_v));

  int tid = threadIdx.x;
  int m0 = blockIdx.y*BM, n0 = blockIdx.x*BN;
  int w = tid>>5, lane = tid&31, g = lane>>2, tg = lane&3;
  int wm = (w>>1)*32, wn = (w&1)*64;

  const float* gA = A + (size_t)m0*D_;
  const float* gB = W + n0;

  float acc[2][8][4];
  #pragma unroll
  for(int i=0;i<2;i++)
    #pragma unroll
    for(int j=0;j<8;j++)
      #pragma unroll
      for(int k=0;k<4;k++) acc[i][j][k]=0.f;

  auto load_tiles = [&](int buf, int kt){
    #pragma unroll
    for(int j=0;j<4;j++){                       // A: 128x32
      int idx = tid + j*256;
      int r = idx>>3, c4 = idx&7;
      cpa16(&As[buf*BM*AST + r*AST + c4*4], gA + (size_t)r*D_ + kt*BK + c4*4);
    }
    #pragma unroll
    for(int j=0;j<4;j++){                       // B: 32x128
      int idx = tid + j*256;
      int r = idx>>5, c4 = idx&31;
      cpa16(&Bs[buf*BK*BST + r*BST + c4*4], gB + (size_t)(kt*BK + r)*D_ + c4*4);
    }
  };

  load_tiles(0,0); cpa_commit();

  #pragma unroll 1
  for(int kt=0; kt<D_/BK; kt++){
    if(kt+1 < D_/BK){ load_tiles((kt+1)&1, kt+1); cpa_commit(); cpa_wait<1>(); }
    else            { cpa_wait<0>(); }
    __syncthreads();
    const float* as = As + (kt&1)*BM*AST;
    const float* bs = Bs + (kt&1)*BK*BST;
    #pragma unroll
    for(int kk=0; kk<BK; kk+=8){
      uint32_t af[2][4], bf[8][2];
      #pragma unroll
      for(int im=0;im<2;im++){
        int rb = wm + im*16;
        af[im][0] = f2tf32(as[(rb+g  )*AST + kk+tg  ]);
        af[im][1] = f2tf32(as[(rb+g+8)*AST + kk+tg  ]);
        af[im][2] = f2tf32(as[(rb+g  )*AST + kk+tg+4]);
        af[im][3] = f2tf32(as[(rb+g+8)*AST + kk+tg+4]);
      }
      #pragma unroll
      for(int in=0;in<8;in++){
        int cb = wn + in*8 + g;
        bf[in][0] = f2tf32(bs[(kk+tg  )*BST + cb]);
        bf[in][1] = f2tf32(bs[(kk+tg+4)*BST + cb]);
      }
      #pragma unroll
      for(int im=0;im<2;im++)
        #pragma unroll
        for(int in=0;in<8;in++)
          mma16n8k8(acc[im][in], af[im], bf[in]);
    }
    __syncthreads();
  }

  #pragma unroll
  for(int im=0;im<2;im++){
    int r0 = m0 + wm + im*16 + g;
    #pragma unroll
    for(int in=0;in<8;in++){
      int col = n0 + wn + in*8 + tg*2;
      float bx = bias[col], by = bias[col+1];
      float2 v0 = make_float2(acc[im][in][0]+bx, acc[im][in][1]+by);
      float2 v1 = make_float2(acc[im][in][2]+bx, acc[im][in][3]+by);
      if(mode==0 || mode==4){
        *(float2*)(Cplain + (size_t)r0*D_ + col)     = v0;
        *(float2*)(Cplain + (size_t)(r0+8)*D_ + col) = v1;
      } else {
        // pre-round to TF32 so flash_attn feeds raw bits to mma
        v0.x = rtf32(v0.x); v0.y = rtf32(v0.y);
        v1.x = rtf32(v1.x); v1.y = rtf32(v1.y);
        int h = col>>6, d = col&63;
        int r8 = r0 + 8;
        size_t i0 = ((size_t)((r0>>12)*H_ + h)*L_ + (r0&4095))*HD_ + d;
        size_t i1 = ((size_t)((r8>>12)*H_ + h)*L_ + (r8&4095))*HD_ + d;
        *(float2*)(C + i0) = v0;
        *(float2*)(C + i1) = v1;
      }
    }
  }
}

// ---------------------------------------------------------------------------
// Flash attention: 1 CTA per (b*h, 128 q rows); 64-key tiles double-buffered.
// Q/K/V in smem are already TF32-rounded -> raw bit loads feed the MMAs.
// ---------------------------------------------------------------------------
constexpr int FM = 128, FN = 64;
constexpr int QST = HD_ + 4;   // 68
constexpr int KST = HD_ + 4;   // 68
constexpr int VST = HD_ + 8;   // 72
constexpr int Q_FLOATS = FM*QST;
constexpr int K_FLOATS = FN*KST;
constexpr int V_FLOATS = FN*VST;
constexpr int FLASH_SMEM = (Q_FLOATS + 2*K_FLOATS + 2*V_FLOATS)*4 + 2*FN*4;

__global__ void __launch_bounds__(256) flash_attn(const int* __restrict__ mask)
{
  extern __shared__ float sm[];
  float* Qs = sm;
  float* Ks = sm + Q_FLOATS;
  float* Vs = Ks + 2*K_FLOATS;
  int*   Ms = (int*)(Vs + 2*V_FLOATS);
  const uint32_t* Qu = (const uint32_t*)Qs;
  const uint32_t* Ku = (const uint32_t*)Ks;
  const uint32_t* Vu = (const uint32_t*)Vs;

  int tid = threadIdx.x, w = tid>>5, lane = tid&31, g = lane>>2, tg = lane&3;
  int bh = blockIdx.y;
  int b  = bh >> 3;
  int q0 = blockIdx.x * FM;

  const float* Qg = g_q + (size_t)bh*L_*HD_ + (size_t)q0*HD_;
  const float* Kg = g_k + (size_t)bh*L_*HD_;
  const float* Vg = g_v + (size_t)bh*L_*HD_;
  const int*   mg = mask + b*L_;

  #pragma unroll
  for(int j=0;j<8;j++){                          // Q tile 128x64
    int idx = tid + j*256;
    int r = idx>>4, c4 = idx&15;
    cpa16(&Qs[r*QST + c4*4], Qg + (size_t)r*HD_ + c4*4);
  }
  cpa_commit();

  auto loadKV = [&](int buf, int it){
    const float* kg = Kg + (size_t)it*FN*HD_;
    const float* vg = Vg + (size_t)it*FN*HD_;
    #pragma unroll
    for(int j=0;j<4;j++){
      int idx = tid + j*256;
      int r = idx>>4, c4 = idx&15;
      cpa16(&Ks[buf*K_FLOATS + r*KST + c4*4], kg + (size_t)r*HD_ + c4*4);
    }
    #pragma unroll
    for(int j=0;j<4;j++){
      int idx = tid + j*256;
      int r = idx>>4, c4 = idx&15;
      cpa16(&Vs[buf*V_FLOATS + r*VST + c4*4], vg + (size_t)r*HD_ + c4*4);
    }
    if(tid < 16) cpa16(&Ms[buf*FN + tid*4], mg + it*FN + tid*4);
  };

  loadKV(0,0); cpa_commit();

  float o[8][4];
  #pragma unroll
  for(int i=0;i<8;i++)
    #pragma unroll
    for(int j=0;j<4;j++) o[i][j]=0.f;
  float mo0=-1e30f, mo1=-1e30f, lo0=0.f, lo1=0.f;

  #pragma unroll 1
  for(int it=0; it<L_/FN; it++){
    int buf = it&1;
    if(it+1 < L_/FN){ loadKV(buf^1, it+1); cpa_commit(); cpa_wait<1>(); }
    else            { cpa_wait<0>(); }
    __syncthreads();

    const uint32_t* ks = Ku + buf*K_FLOATS;
    const uint32_t* vs = Vu + buf*V_FLOATS;
    const int*      ms = Ms + buf*FN;

    // S = Q @ K^T (per warp: 16 q-rows x 64 keys) — raw TF32 bit loads
    float s[8][4];
    #pragma unroll
    for(int i=0;i<8;i++)
      #pragma unroll
      for(int j=0;j<4;j++) s[i][j]=0.f;

    #pragma unroll
    for(int kk=0; kk<HD_; kk+=8){
      uint32_t af[4];
      int rb = w*16;
      af[0] = Qu[(rb+g  )*QST + kk+tg  ];
      af[1] = Qu[(rb+g+8)*QST + kk+tg  ];
      af[2] = Qu[(rb+g  )*QST + kk+tg+4];
      af[3] = Qu[(rb+g+8)*QST + kk+tg+4];
      #pragma unroll
      for(int in=0;in<8;in++){
        uint32_t bf[2];
        bf[0] = ks[(in*8+g)*KST + kk+tg  ];
        bf[1] = ks[(in*8+g)*KST + kk+tg+4];
        mma16n8k8(s[in], af, bf);
      }
    }

    const float scale = 0.125f;   // 1/sqrt(64)
    #pragma unroll
    for(int in=0;in<8;in++){
      int c0 = in*8 + tg*2;
      bool ok0 = ms[c0]!=0, ok1 = ms[c0+1]!=0;
      s[in][0] = ok0 ? s[in][0]*scale : -1e30f;
      s[in][1] = ok1 ? s[in][1]*scale : -1e30f;
      s[in][2] = ok0 ? s[in][2]*scale : -1e30f;
      s[in][3] = ok1 ? s[in][3]*scale : -1e30f;
    }

    // online softmax; rows (w*16+g) and (+8) live within one quad
    float mx0=-1e30f, mx1=-1e30f;
    #pragma unroll
    for(int in=0;in<8;in++){
      mx0 = fmaxf(mx0, fmaxf(s[in][0], s[in][1]));
      mx1 = fmaxf(mx1, fmaxf(s[in][2], s[in][3]));
    }
    mx0 = fmaxf(mx0, __shfl_xor_sync(0xffffffffu, mx0, 1));
    mx0 = fmaxf(mx0, __shfl_xor_sync(0xffffffffu, mx0, 2));
    mx1 = fmaxf(mx1, __shfl_xor_sync(0xffffffffu, mx1, 1));
    mx1 = fmaxf(mx1, __shfl_xor_sync(0xffffffffu, mx1, 2));

    float mn0 = fmaxf(mo0, mx0), mn1 = fmaxf(mo1, mx1);
    float sc0 = __expf(mo0 - mn0), sc1 = __expf(mo1 - mn1);

    float rs0=0.f, rs1=0.f;
    #pragma unroll
    for(int in=0;in<8;in++){
      s[in][0] = __expf(s[in][0]-mn0); rs0 += s[in][0];
      s[in][1] = __expf(s[in][1]-mn0); rs0 += s[in][1];
      s[in][2] = __expf(s[in][2]-mn1); rs1 += s[in][2];
      s[in][3] = __expf(s[in][3]-mn1); rs1 += s[in][3];
    }
    rs0 += __shfl_xor_sync(0xffffffffu, rs0, 1);
    rs0 += __shfl_xor_sync(0xffffffffu, rs0, 2);
    rs1 += __shfl_xor_sync(0xffffffffu, rs1, 1);
    rs1 += __shfl_xor_sync(0xffffffffu, rs1, 2);

    lo0 = lo0*sc0 + rs0;
    lo1 = lo1*sc1 + rs1;
    mo0 = mn0; mo1 = mn1;

    #pragma unroll
    for(int in=0;in<8;in++){
      o[in][0]*=sc0; o[in][1]*=sc0; o[in][2]*=sc1; o[in][3]*=sc1;
    }

    // O += P @ V ; P C-frag -> A-frag via width-4 shuffles (P gets RNA cvt)
    #pragma unroll
    for(int kb=0;kb<8;kb++){
      int src  = tg>>1;
      int src2 = src + 2;
      float x0 = __shfl_sync(0xffffffffu, s[kb][0], src , 4);
      float x1 = __shfl_sync(0xffffffffu, s[kb][1], src , 4);
      float x2 = __shfl_sync(0xffffffffu, s[kb][2], src , 4);
      float x3 = __shfl_sync(0xffffffffu, s[kb][3], src , 4);
      float y0 = __shfl_sync(0xffffffffu, s[kb][0], src2, 4);
      float y1 = __shfl_sync(0xffffffffu, s[kb][1], src2, 4);
      float y2 = __shfl_sync(0xffffffffu, s[kb][2], src2, 4);
      float y3 = __shfl_sync(0xffffffffu, s[kb][3], src2, 4);
      bool odd = (tg&1)!=0;
      uint32_t af[4];
      af[0] = f2tf32(odd ? x1 : x0);
      af[1] = f2tf32(odd ? x3 : x2);
      af[2] = f2tf32(odd ? y1 : y0);
      af[3] = f2tf32(odd ? y3 : y2);
      #pragma unroll
      for(int in=0;in<8;in++){
        uint32_t bf[2];
        bf[0] = vs[(kb*8+tg  )*VST + in*8+g];
        bf[1] = vs[(kb*8+tg+4)*VST + in*8+g];
        mma16n8k8(o[in], af, bf);
      }
    }
    __syncthreads();
  }

  float inv0 = 1.f/lo0, inv1 = 1.f/lo1;
  int r0 = q0 + w*16 + g;
  float* op0 = g_ctx + (size_t)(b*L_ + r0    )*D_ + (bh&7)*HD_;
  float* op1 = g_ctx + (size_t)(b*L_ + r0 + 8)*D_ + (bh&7)*HD_;
  #pragma unroll
  for(int in=0;in<8;in++){
    int d = in*8 + tg*2;
    *(float2*)(op0 + d) = make_float2(o[in][0]*inv0, o[in][1]*inv0);
    *(float2*)(op1 + d) = make_float2(o[in][2]*inv1, o[in][3]*inv1);
  }
}

// ---------------------------------------------------------------------------
extern "C" void kernel_launch(void* const* d_in, const int* in_sizes, int n_in,
                              void* d_out, int out_size)
{
  (void)in_sizes; (void)n_in; (void)out_size;
  const float* query = (const float*)d_in[0];
  const float* key   = (const float*)d_in[1];
  const float* value = (const float*)d_in[2];
  const int*   mask  = (const int*)d_in[3];
  const float* Wq = (const float*)d_in[4];
  const float* bq = (const float*)d_in[5];
  const float* Wk = (const float*)d_in[6];
  const float* bk = (const float*)d_in[7];
  const float* Wv = (const float*)d_in[8];
  const float* bv = (const float*)d_in[9];
  const float* Wo = (const float*)d_in[10];
  const float* bo = (const float*)d_in[11];
  float* out = (float*)d_out;

  static bool attr_done = false;
  if(!attr_done){
    cudaFuncSetAttribute(gemm_tf32,  cudaFuncAttributeMaxDynamicSharedMemorySize, GEMM_SMEM);
    cudaFuncSetAttribute(flash_attn, cudaFuncAttributeMaxDynamicSharedMemorySize, FLASH_SMEM);
    attr_done = true;
  }

  dim3 gg(D_/BN, M_/BM);            // (4, 64)
  gemm_tf32<<<gg, 256, GEMM_SMEM>>>(query, Wq, bq, nullptr, 1);
  gemm_tf32<<<gg, 256, GEMM_SMEM>>>(key,   Wk, bk, nullptr, 2);
  gemm_tf32<<<gg, 256, GEMM_SMEM>>>(value, Wv, bv, nullptr, 3);

  dim3 fg(L_/FM, B_*H_);            // (32, 16)
  flash_attn<<<fg, 256, FLASH_SMEM>>>(mask);

  gemm_tf32<<<gg, 256, GEMM_SMEM>>>(nullptr, Wo, bo, out, 4);
}

// round 5
// speedup vs baseline: 1.7883x; 1.5636x over previous
#include <cuda_runtime.h>
#include <cuda_fp16.h>
#include <cstdint>

#define DEVI __device__ __forceinline__

constexpr int B_  = 2;
constexpr int L_  = 4096;
constexpr int D_  = 512;
constexpr int H_  = 8;
constexpr int HD_ = 64;
constexpr int M_  = B_ * L_;   // 8192

// scratch: __device__ globals (allocation-free rule)
__device__ __half g_qh[B_*H_*L_*HD_];   // [b,h,l,d]
__device__ __half g_kh[B_*H_*L_*HD_];   // [b,h,l,d]
__device__ __half g_vt[B_*H_*HD_*L_];   // [b,h,d,l]  (transposed)
__device__ float  g_ctx[M_*D_];

DEVI uint32_t f2tf32(float x){ uint32_t r; asm("cvt.rna.tf32.f32 %0, %1;":"=r"(r):"f"(x)); return r; }
DEVI uint32_t h2u(__half2 h){ union{ __half2 h; uint32_t u; } c; c.h = h; return c.u; }

DEVI void mma_tf32(float* c, const uint32_t* a, const uint32_t* b){
  asm volatile("mma.sync.aligned.m16n8k8.row.col.f32.tf32.tf32.f32 "
    "{%0,%1,%2,%3},{%4,%5,%6,%7},{%8,%9},{%0,%1,%2,%3};\n"
    : "+f"(c[0]),"+f"(c[1]),"+f"(c[2]),"+f"(c[3])
    : "r"(a[0]),"r"(a[1]),"r"(a[2]),"r"(a[3]),"r"(b[0]),"r"(b[1]));
}

DEVI void mma_f16(float* c, const uint32_t* a, const uint32_t* b){
  asm volatile("mma.sync.aligned.m16n8k16.row.col.f32.f16.f16.f32 "
    "{%0,%1,%2,%3},{%4,%5,%6,%7},{%8,%9},{%0,%1,%2,%3};\n"
    : "+f"(c[0]),"+f"(c[1]),"+f"(c[2]),"+f"(c[3])
    : "r"(a[0]),"r"(a[1]),"r"(a[2]),"r"(a[3]),"r"(b[0]),"r"(b[1]));
}

DEVI void cpa16(void* s, const void* g){
  uint32_t sa = (uint32_t)__cvta_generic_to_shared(s);
  asm volatile("cp.async.cg.shared.global [%0], [%1], 16;\n"::"r"(sa),"l"(g));
}
DEVI void cpa_commit(){ asm volatile("cp.async.commit_group;\n"); }
template<int N> DEVI void cpa_wait(){ asm volatile("cp.async.wait_group %0;\n"::"n"(N)); }

// ---------------------------------------------------------------------------
// TF32 GEMM: C[M,512] = A[M,512] @ W[512,512] + bias
// mode 4: A = g_ctx, plain f32 out.  mode 1/2: fp16 scatter to g_qh/g_kh.
// mode 3: fp16 transposed scatter to g_vt.
// ---------------------------------------------------------------------------
constexpr int BM = 128, BN = 128, BK = 32;
constexpr int AST = BK + 4;    // 36
constexpr int BST = BN + 8;    // 136
constexpr int GEMM_SMEM = (2*BM*AST + 2*BK*BST) * 4;

__global__ void __launch_bounds__(256,2) gemm_tf32(
  const float* __restrict__ Ain, const float* __restrict__ W,
  const float* __restrict__ bias, float* __restrict__ Cplain, int mode)
{
  extern __shared__ float sm[];
  float* As = sm;                  // [2][BM][AST]
  float* Bs = sm + 2*BM*AST;       // [2][BK][BST]
  const float* A = (mode==4) ? g_ctx : Ain;

  int tid = threadIdx.x;
  int m0 = blockIdx.y*BM, n0 = blockIdx.x*BN;
  int w = tid>>5, lane = tid&31, g = lane>>2, tg = lane&3;
  int wm = (w>>1)*32, wn = (w&1)*64;

  const float* gA = A + (size_t)m0*D_;
  const float* gB = W + n0;

  float acc[2][8][4];
  #pragma unroll
  for(int i=0;i<2;i++)
    #pragma unroll
    for(int j=0;j<8;j++)
      #pragma unroll
      for(int k=0;k<4;k++) acc[i][j][k]=0.f;

  auto load_tiles = [&](int buf, int kt){
    #pragma unroll
    for(int j=0;j<4;j++){                       // A: 128x32
      int idx = tid + j*256;
      int r = idx>>3, c4 = idx&7;
      cpa16(&As[buf*BM*AST + r*AST + c4*4], gA + (size_t)r*D_ + kt*BK + c4*4);
    }
    #pragma unroll
    for(int j=0;j<4;j++){                       // B: 32x128
      int idx = tid + j*256;
      int r = idx>>5, c4 = idx&31;
      cpa16(&Bs[buf*BK*BST + r*BST + c4*4], gB + (size_t)(kt*BK + r)*D_ + c4*4);
    }
  };

  load_tiles(0,0); cpa_commit();

  #pragma unroll 1
  for(int kt=0; kt<D_/BK; kt++){
    if(kt+1 < D_/BK){ load_tiles((kt+1)&1, kt+1); cpa_commit(); cpa_wait<1>(); }
    else            { cpa_wait<0>(); }
    __syncthreads();
    const float* as = As + (kt&1)*BM*AST;
    const float* bs = Bs + (kt&1)*BK*BST;
    #pragma unroll
    for(int kk=0; kk<BK; kk+=8){
      uint32_t af[2][4], bf[8][2];
      #pragma unroll
      for(int im=0;im<2;im++){
        int rb = wm + im*16;
        af[im][0] = f2tf32(as[(rb+g  )*AST + kk+tg  ]);
        af[im][1] = f2tf32(as[(rb+g+8)*AST + kk+tg  ]);
        af[im][2] = f2tf32(as[(rb+g  )*AST + kk+tg+4]);
        af[im][3] = f2tf32(as[(rb+g+8)*AST + kk+tg+4]);
      }
      #pragma unroll
      for(int in=0;in<8;in++){
        int cb = wn + in*8 + g;
        bf[in][0] = f2tf32(bs[(kk+tg  )*BST + cb]);
        bf[in][1] = f2tf32(bs[(kk+tg+4)*BST + cb]);
      }
      #pragma unroll
      for(int im=0;im<2;im++)
        #pragma unroll
        for(int in=0;in<8;in++)
          mma_tf32(acc[im][in], af[im], bf[in]);
    }
    __syncthreads();
  }

  #pragma unroll
  for(int im=0;im<2;im++){
    int r0 = m0 + wm + im*16 + g;
    int r8 = r0 + 8;
    #pragma unroll
    for(int in=0;in<8;in++){
      int col = n0 + wn + in*8 + tg*2;
      float bx = bias[col], by = bias[col+1];
      float2 v0 = make_float2(acc[im][in][0]+bx, acc[im][in][1]+by);
      float2 v1 = make_float2(acc[im][in][2]+bx, acc[im][in][3]+by);
      if(mode==4){
        *(float2*)(Cplain + (size_t)r0*D_ + col) = v0;
        *(float2*)(Cplain + (size_t)r8*D_ + col) = v1;
      } else {
        int h = col>>6, d = col&63;
        int b0i = r0>>12, t0 = r0&4095;
        int b1i = r8>>12, t1 = r8&4095;
        if(mode==3){
          // V transposed: [b,h,d,l]
          size_t i0 = ((size_t)(b0i*H_ + h)*HD_ + d)*L_ + t0;
          size_t i1 = ((size_t)(b1i*H_ + h)*HD_ + d)*L_ + t1;
          g_vt[i0]      = __float2half_rn(v0.x);
          g_vt[i0 + L_] = __float2half_rn(v0.y);
          g_vt[i1]      = __float2half_rn(v1.x);
          g_vt[i1 + L_] = __float2half_rn(v1.y);
        } else {
          __half* C = (mode==1) ? g_qh : g_kh;
          size_t i0 = ((size_t)(b0i*H_ + h)*L_ + t0)*HD_ + d;
          size_t i1 = ((size_t)(b1i*H_ + h)*L_ + t1)*HD_ + d;
          *(__half2*)(C + i0) = __floats2half2_rn(v0.x, v0.y);
          *(__half2*)(C + i1) = __floats2half2_rn(v1.x, v1.y);
        }
      }
    }
  }
}

// ---------------------------------------------------------------------------
// Flash attention, fp16 operands / fp32 accum.
// 1 CTA per (b*h, 128 q rows); 64-key K and V^T tiles double-buffered.
// smem row stride = 36 words (72 halves): bank = g*4+tg, conflict-free.
// ---------------------------------------------------------------------------
constexpr int FM = 128, FN = 64;
constexpr int RSW = 36;                 // row stride in 32-bit words
constexpr int Q_WORDS = FM*RSW;         // 4608
constexpr int K_WORDS = FN*RSW;         // 2304
constexpr int V_WORDS = FN*RSW;         // 2304
constexpr int FLASH_SMEM = (Q_WORDS + 2*K_WORDS + 2*V_WORDS)*4 + 2*FN*4;

__global__ void __launch_bounds__(256,2) flash_attn(const int* __restrict__ mask)
{
  extern __shared__ uint32_t smw[];
  uint32_t* Qw = smw;                    // [128][36]
  uint32_t* Kw = smw + Q_WORDS;          // [2][64][36]
  uint32_t* Vw = Kw + 2*K_WORDS;         // [2][64][36]  (V^T: row=d, col=key)
  int*      Ms = (int*)(Vw + 2*V_WORDS);

  int tid = threadIdx.x, w = tid>>5, lane = tid&31, g = lane>>2, tg = lane&3;
  int bh = blockIdx.y;
  int b  = bh >> 3;
  int q0 = blockIdx.x * FM;

  const __half* Qg = g_qh + (size_t)bh*L_*HD_ + (size_t)q0*HD_;
  const __half* Kg = g_kh + (size_t)bh*L_*HD_;
  const __half* Vg = g_vt + (size_t)bh*HD_*L_;
  const int*    mg = mask + b*L_;

  // Q tile: 128 rows x 64 halves (128B/row -> 8 cpa16 chunks/row)
  #pragma unroll
  for(int j=0;j<4;j++){
    int idx = tid + j*256;
    int r = idx>>3, c = idx&7;
    cpa16((char*)(Qw + r*RSW) + c*16, Qg + (size_t)r*HD_ + c*8);
  }
  cpa_commit();

  auto loadKV = [&](int buf, int it){
    const __half* kg = Kg + (size_t)it*FN*HD_;
    const __half* vg = Vg + it*FN;          // V^T: column offset
    #pragma unroll
    for(int j=0;j<2;j++){                   // K: 64 rows x 64 halves
      int idx = tid + j*256;
      int r = idx>>3, c = idx&7;
      cpa16((char*)(Kw + buf*K_WORDS + r*RSW) + c*16, kg + (size_t)r*HD_ + c*8);
    }
    #pragma unroll
    for(int j=0;j<2;j++){                   // V^T: 64 d-rows x 64 keys
      int idx = tid + j*256;
      int r = idx>>3, c = idx&7;
      cpa16((char*)(Vw + buf*V_WORDS + r*RSW) + c*16, vg + (size_t)r*L_ + c*8);
    }
    if(tid < 16) cpa16(&Ms[buf*FN + tid*4], mg + it*FN + tid*4);
  };

  loadKV(0,0); cpa_commit();

  float o[8][4];
  #pragma unroll
  for(int i=0;i<8;i++)
    #pragma unroll
    for(int j=0;j<4;j++) o[i][j]=0.f;
  float mo0=-1e30f, mo1=-1e30f, lo0=0.f, lo1=0.f;

  #pragma unroll 1
  for(int it=0; it<L_/FN; it++){
    int buf = it&1;
    if(it+1 < L_/FN){ loadKV(buf^1, it+1); cpa_commit(); cpa_wait<1>(); }
    else            { cpa_wait<0>(); }
    __syncthreads();

    const uint32_t* ks = Kw + buf*K_WORDS;
    const uint32_t* vs = Vw + buf*V_WORDS;
    const int*      ms = Ms + buf*FN;

    // S = Q @ K^T : 4 k16 steps over HD=64
    float s[8][4];
    #pragma unroll
    for(int i=0;i<8;i++)
      #pragma unroll
      for(int j=0;j<4;j++) s[i][j]=0.f;

    int rb = w*16;
    #pragma unroll
    for(int kk=0; kk<4; kk++){
      int kw = kk*8;
      uint32_t af[4];
      af[0] = Qw[(rb+g  )*RSW + kw+tg  ];
      af[1] = Qw[(rb+g+8)*RSW + kw+tg  ];
      af[2] = Qw[(rb+g  )*RSW + kw+tg+4];
      af[3] = Qw[(rb+g+8)*RSW + kw+tg+4];
      #pragma unroll
      for(int in=0;in<8;in++){
        uint32_t bf[2];
        bf[0] = ks[(in*8+g)*RSW + kw+tg  ];
        bf[1] = ks[(in*8+g)*RSW + kw+tg+4];
        mma_f16(s[in], af, bf);
      }
    }

    const float scale = 0.125f;   // 1/sqrt(64)
    #pragma unroll
    for(int in=0;in<8;in++){
      int c0 = in*8 + tg*2;
      bool ok0 = ms[c0]!=0, ok1 = ms[c0+1]!=0;
      s[in][0] = ok0 ? s[in][0]*scale : -1e30f;
      s[in][1] = ok1 ? s[in][1]*scale : -1e30f;
      s[in][2] = ok0 ? s[in][2]*scale : -1e30f;
      s[in][3] = ok1 ? s[in][3]*scale : -1e30f;
    }

    // online softmax; rows (w*16+g) and (+8) live within one quad
    float mx0=-1e30f, mx1=-1e30f;
    #pragma unroll
    for(int in=0;in<8;in++){
      mx0 = fmaxf(mx0, fmaxf(s[in][0], s[in][1]));
      mx1 = fmaxf(mx1, fmaxf(s[in][2], s[in][3]));
    }
    mx0 = fmaxf(mx0, __shfl_xor_sync(0xffffffffu, mx0, 1));
    mx0 = fmaxf(mx0, __shfl_xor_sync(0xffffffffu, mx0, 2));
    mx1 = fmaxf(mx1, __shfl_xor_sync(0xffffffffu, mx1, 1));
    mx1 = fmaxf(mx1, __shfl_xor_sync(0xffffffffu, mx1, 2));

    float mn0 = fmaxf(mo0, mx0), mn1 = fmaxf(mo1, mx1);
    float sc0 = __expf(mo0 - mn0), sc1 = __expf(mo1 - mn1);

    float rs0=0.f, rs1=0.f;
    #pragma unroll
    for(int in=0;in<8;in++){
      s[in][0] = __expf(s[in][0]-mn0); rs0 += s[in][0];
      s[in][1] = __expf(s[in][1]-mn0); rs0 += s[in][1];
      s[in][2] = __expf(s[in][2]-mn1); rs1 += s[in][2];
      s[in][3] = __expf(s[in][3]-mn1); rs1 += s[in][3];
    }
    rs0 += __shfl_xor_sync(0xffffffffu, rs0, 1);
    rs0 += __shfl_xor_sync(0xffffffffu, rs0, 2);
    rs1 += __shfl_xor_sync(0xffffffffu, rs1, 1);
    rs1 += __shfl_xor_sync(0xffffffffu, rs1, 2);

    lo0 = lo0*sc0 + rs0;
    lo1 = lo1*sc1 + rs1;
    mo0 = mn0; mo1 = mn1;

    #pragma unroll
    for(int in=0;in<8;in++){
      o[in][0]*=sc0; o[in][1]*=sc0; o[in][2]*=sc1; o[in][3]*=sc1;
    }

    // O += P @ V : S C-frags map directly onto fp16 k16 A-frags (no shuffles)
    #pragma unroll
    for(int kb=0;kb<4;kb++){
      uint32_t ap[4];
      ap[0] = h2u(__floats2half2_rn(s[2*kb  ][0], s[2*kb  ][1]));
      ap[1] = h2u(__floats2half2_rn(s[2*kb  ][2], s[2*kb  ][3]));
      ap[2] = h2u(__floats2half2_rn(s[2*kb+1][0], s[2*kb+1][1]));
      ap[3] = h2u(__floats2half2_rn(s[2*kb+1][2], s[2*kb+1][3]));
      #pragma unroll
      for(int in=0;in<8;in++){
        uint32_t bf[2];
        bf[0] = vs[(in*8+g)*RSW + kb*8+tg  ];
        bf[1] = vs[(in*8+g)*RSW + kb*8+tg+4];
        mma_f16(o[in], ap, bf);
      }
    }
    __syncthreads();
  }

  float inv0 = 1.f/lo0, inv1 = 1.f/lo1;
  int r0 = q0 + w*16 + g;
  float* op0 = g_ctx + (size_t)(b*L_ + r0    )*D_ + (bh&7)*HD_;
  float* op1 = g_ctx + (size_t)(b*L_ + r0 + 8)*D_ + (bh&7)*HD_;
  #pragma unroll
  for(int in=0;in<8;in++){
    int d = in*8 + tg*2;
    *(float2*)(op0 + d) = make_float2(o[in][0]*inv0, o[in][1]*inv0);
    *(float2*)(op1 + d) = make_float2(o[in][2]*inv1, o[in][3]*inv1);
  }
}

// ---------------------------------------------------------------------------
extern "C" void kernel_launch(void* const* d_in, const int* in_sizes, int n_in,
                              void* d_out, int out_size)
{
  (void)in_sizes; (void)n_in; (void)out_size;
  const float* query = (const float*)d_in[0];
  const float* key   = (const float*)d_in[1];
  const float* value = (const float*)d_in[2];
  const int*   mask  = (const int*)d_in[3];
  const float* Wq = (const float*)d_in[4];
  const float* bq = (const float*)d_in[5];
  const float* Wk = (const float*)d_in[6];
  const float* bk = (const float*)d_in[7];
  const float* Wv = (const float*)d_in[8];
  const float* bv = (const float*)d_in[9];
  const float* Wo = (const float*)d_in[10];
  const float* bo = (const float*)d_in[11];
  float* out = (float*)d_out;

  static bool attr_done = false;
  if(!attr_done){
    cudaFuncSetAttribute(gemm_tf32,  cudaFuncAttributeMaxDynamicSharedMemorySize, GEMM_SMEM);
    cudaFuncSetAttribute(flash_attn, cudaFuncAttributeMaxDynamicSharedMemorySize, FLASH_SMEM);
    attr_done = true;
  }

  dim3 gg(D_/BN, M_/BM);            // (4, 64)
  gemm_tf32<<<gg, 256, GEMM_SMEM>>>(query, Wq, bq, nullptr, 1);
  gemm_tf32<<<gg, 256, GEMM_SMEM>>>(key,   Wk, bk, nullptr, 2);
  gemm_tf32<<<gg, 256, GEMM_SMEM>>>(value, Wv, bv, nullptr, 3);

  dim3 fg(L_/FM, B_*H_);            // (32, 16)
  flash_attn<<<fg, 256, FLASH_SMEM>>>(mask);

  gemm_tf32<<<gg, 256, GEMM_SMEM>>>(nullptr, Wo, bo, out, 4);
}

// round 6
// speedup vs baseline: 1.9175x; 1.0723x over previous
#include <cuda_runtime.h>
#include <cuda_fp16.h>
#include <cstdint>

#define DEVI __device__ __forceinline__

constexpr int B_  = 2;
constexpr int L_  = 4096;
constexpr int D_  = 512;
constexpr int H_  = 8;
constexpr int HD_ = 64;
constexpr int M_  = B_ * L_;   // 8192

// scratch: __device__ globals (allocation-free rule)
__device__ __half g_qh[B_*H_*L_*HD_];   // [b,h,l,d] (pre-scaled by 0.125)
__device__ __half g_kh[B_*H_*L_*HD_];   // [b,h,l,d]
__device__ __half g_vt[B_*H_*HD_*L_];   // [b,h,d,l]  (transposed)
__device__ float  g_ctx[M_*D_];

DEVI uint32_t f2tf32(float x){ uint32_t r; asm("cvt.rna.tf32.f32 %0, %1;":"=r"(r):"f"(x)); return r; }
DEVI uint32_t h2u(__half2 h){ union{ __half2 h; uint32_t u; } c; c.h = h; return c.u; }

DEVI void mma_tf32(float* c, const uint32_t* a, const uint32_t* b){
  asm volatile("mma.sync.aligned.m16n8k8.row.col.f32.tf32.tf32.f32 "
    "{%0,%1,%2,%3},{%4,%5,%6,%7},{%8,%9},{%0,%1,%2,%3};\n"
    : "+f"(c[0]),"+f"(c[1]),"+f"(c[2]),"+f"(c[3])
    : "r"(a[0]),"r"(a[1]),"r"(a[2]),"r"(a[3]),"r"(b[0]),"r"(b[1]));
}

DEVI void mma_f16(float* c, const uint32_t* a, const uint32_t* b){
  asm volatile("mma.sync.aligned.m16n8k16.row.col.f32.f16.f16.f32 "
    "{%0,%1,%2,%3},{%4,%5,%6,%7},{%8,%9},{%0,%1,%2,%3};\n"
    : "+f"(c[0]),"+f"(c[1]),"+f"(c[2]),"+f"(c[3])
    : "r"(a[0]),"r"(a[1]),"r"(a[2]),"r"(a[3]),"r"(b[0]),"r"(b[1]));
}

DEVI void ldsm4(uint32_t& r0, uint32_t& r1, uint32_t& r2, uint32_t& r3, uint32_t addr){
  asm volatile("ldmatrix.sync.aligned.m8n8.x4.shared.b16 {%0,%1,%2,%3}, [%4];"
    : "=r"(r0),"=r"(r1),"=r"(r2),"=r"(r3) : "r"(addr));
}

DEVI void cpa16(void* s, const void* g){
  uint32_t sa = (uint32_t)__cvta_generic_to_shared(s);
  asm volatile("cp.async.cg.shared.global [%0], [%1], 16;\n"::"r"(sa),"l"(g));
}
DEVI void cpa_commit(){ asm volatile("cp.async.commit_group;\n"); }
template<int N> DEVI void cpa_wait(){ asm volatile("cp.async.wait_group %0;\n"::"n"(N)); }

// ---------------------------------------------------------------------------
// TF32 GEMM: C[M,512] = A[M,512] @ W[512,512] + bias
// mode 4: A = g_ctx, plain f32 out.  mode 1/2: fp16 scatter to g_qh/g_kh
// (mode 1 additionally scales by 0.125 == 1/sqrt(HD), exact power of 2).
// mode 3: fp16 transposed scatter to g_vt.
// ---------------------------------------------------------------------------
constexpr int BM = 128, BN = 128, BK = 32;
constexpr int AST = BK + 4;    // 36
constexpr int BST = BN + 8;    // 136
constexpr int GEMM_SMEM = (2*BM*AST + 2*BK*BST) * 4;

__global__ void __launch_bounds__(256,2) gemm_tf32(
  const float* __restrict__ Ain, const float* __restrict__ W,
  const float* __restrict__ bias, float* __restrict__ Cplain, int mode)
{
  extern __shared__ float sm[];
  float* As = sm;                  // [2][BM][AST]
  float* Bs = sm + 2*BM*AST;       // [2][BK][BST]
  const float* A = (mode==4) ? g_ctx : Ain;

  int tid = threadIdx.x;
  int m0 = blockIdx.y*BM, n0 = blockIdx.x*BN;
  int w = tid>>5, lane = tid&31, g = lane>>2, tg = lane&3;
  int wm = (w>>1)*32, wn = (w&1)*64;

  const float* gA = A + (size_t)m0*D_;
  const float* gB = W + n0;

  float acc[2][8][4];
  #pragma unroll
  for(int i=0;i<2;i++)
    #pragma unroll
    for(int j=0;j<8;j++)
      #pragma unroll
      for(int k=0;k<4;k++) acc[i][j][k]=0.f;

  auto load_tiles = [&](int buf, int kt){
    #pragma unroll
    for(int j=0;j<4;j++){                       // A: 128x32
      int idx = tid + j*256;
      int r = idx>>3, c4 = idx&7;
      cpa16(&As[buf*BM*AST + r*AST + c4*4], gA + (size_t)r*D_ + kt*BK + c4*4);
    }
    #pragma unroll
    for(int j=0;j<4;j++){                       // B: 32x128
      int idx = tid + j*256;
      int r = idx>>5, c4 = idx&31;
      cpa16(&Bs[buf*BK*BST + r*BST + c4*4], gB + (size_t)(kt*BK + r)*D_ + c4*4);
    }
  };

  load_tiles(0,0); cpa_commit();

  #pragma unroll 1
  for(int kt=0; kt<D_/BK; kt++){
    if(kt+1 < D_/BK){ load_tiles((kt+1)&1, kt+1); cpa_commit(); cpa_wait<1>(); }
    else            { cpa_wait<0>(); }
    __syncthreads();
    const float* as = As + (kt&1)*BM*AST;
    const float* bs = Bs + (kt&1)*BK*BST;
    #pragma unroll
    for(int kk=0; kk<BK; kk+=8){
      uint32_t af[2][4], bf[8][2];
      #pragma unroll
      for(int im=0;im<2;im++){
        int rb = wm + im*16;
        af[im][0] = f2tf32(as[(rb+g  )*AST + kk+tg  ]);
        af[im][1] = f2tf32(as[(rb+g+8)*AST + kk+tg  ]);
        af[im][2] = f2tf32(as[(rb+g  )*AST + kk+tg+4]);
        af[im][3] = f2tf32(as[(rb+g+8)*AST + kk+tg+4]);
      }
      #pragma unroll
      for(int in=0;in<8;in++){
        int cb = wn + in*8 + g;
        bf[in][0] = f2tf32(bs[(kk+tg  )*BST + cb]);
        bf[in][1] = f2tf32(bs[(kk+tg+4)*BST + cb]);
      }
      #pragma unroll
      for(int im=0;im<2;im++)
        #pragma unroll
        for(int in=0;in<8;in++)
          mma_tf32(acc[im][in], af[im], bf[in]);
    }
    __syncthreads();
  }

  float oscale = (mode==1) ? 0.125f : 1.0f;
  #pragma unroll
  for(int im=0;im<2;im++){
    int r0 = m0 + wm + im*16 + g;
    int r8 = r0 + 8;
    #pragma unroll
    for(int in=0;in<8;in++){
      int col = n0 + wn + in*8 + tg*2;
      float bx = bias[col], by = bias[col+1];
      float2 v0 = make_float2(acc[im][in][0]+bx, acc[im][in][1]+by);
      float2 v1 = make_float2(acc[im][in][2]+bx, acc[im][in][3]+by);
      if(mode==4){
        *(float2*)(Cplain + (size_t)r0*D_ + col) = v0;
        *(float2*)(Cplain + (size_t)r8*D_ + col) = v1;
      } else {
        int h = col>>6, d = col&63;
        int b0i = r0>>12, t0 = r0&4095;
        int b1i = r8>>12, t1 = r8&4095;
        if(mode==3){
          // V transposed: [b,h,d,l]
          size_t i0 = ((size_t)(b0i*H_ + h)*HD_ + d)*L_ + t0;
          size_t i1 = ((size_t)(b1i*H_ + h)*HD_ + d)*L_ + t1;
          g_vt[i0]      = __float2half_rn(v0.x);
          g_vt[i0 + L_] = __float2half_rn(v0.y);
          g_vt[i1]      = __float2half_rn(v1.x);
          g_vt[i1 + L_] = __float2half_rn(v1.y);
        } else {
          __half* C = (mode==1) ? g_qh : g_kh;
          size_t i0 = ((size_t)(b0i*H_ + h)*L_ + t0)*HD_ + d;
          size_t i1 = ((size_t)(b1i*H_ + h)*L_ + t1)*HD_ + d;
          *(__half2*)(C + i0) = __floats2half2_rn(v0.x*oscale, v0.y*oscale);
          *(__half2*)(C + i1) = __floats2half2_rn(v1.x*oscale, v1.y*oscale);
        }
      }
    }
  }
}

// ---------------------------------------------------------------------------
// Flash attention, fp16 operands / fp32 accum, LDSM fragment loads.
// 1 CTA per (b*h, 128 q rows); 64-key K and V^T tiles double-buffered.
// smem row stride = 36 words: rows shift 4 banks -> LDSM phases conflict-free.
// ---------------------------------------------------------------------------
constexpr int FM = 128, FN = 64;
constexpr int RSW = 36;                 // row stride in 32-bit words
constexpr int Q_WORDS = FM*RSW;         // 4608
constexpr int K_WORDS = FN*RSW;         // 2304
constexpr int V_WORDS = FN*RSW;         // 2304
constexpr int FLASH_SMEM = (Q_WORDS + 2*K_WORDS + 2*V_WORDS)*4 + 2*FN*4;

__global__ void __launch_bounds__(256,2) flash_attn(const int* __restrict__ mask)
{
  extern __shared__ uint32_t smw[];
  uint32_t* Qw = smw;                    // [128][36]
  uint32_t* Kw = smw + Q_WORDS;          // [2][64][36]
  uint32_t* Vw = Kw + 2*K_WORDS;         // [2][64][36]  (V^T: row=d, col=key)
  int*      Ms = (int*)(Vw + 2*V_WORDS);

  int tid = threadIdx.x, w = tid>>5, lane = tid&31, g = lane>>2, tg = lane&3;
  int bh = blockIdx.y;
  int b  = bh >> 3;
  int q0 = blockIdx.x * FM;
  int rb = w*16;

  const __half* Qg = g_qh + (size_t)bh*L_*HD_ + (size_t)q0*HD_;
  const __half* Kg = g_kh + (size_t)bh*L_*HD_;
  const __half* Vg = g_vt + (size_t)bh*HD_*L_;
  const int*    mg = mask + b*L_;

  // ---- LDSM per-thread addresses (bytes, shared address space) ----
  uint32_t smem_base = (uint32_t)__cvta_generic_to_shared(smw);
  int t8  = lane & 7;
  int lb1 = (lane>>3) & 1;
  int lb2 = lane>>4;
  // Q x4: matrices (rowblk rb/rb+8) x (word-chunk 0/4):
  //   m0:rows rb..+7 ch0 | m1:rows rb+8..+15 ch0 | m2:rows rb ch1 | m3:rows rb+8 ch1
  uint32_t qaddr = smem_base + (uint32_t)((rb + lb1*8 + t8)*RSW + lb2*4)*4;
  // K/V x4: matrices (in,ch0),(in,ch1),(in+1,ch0),(in+1,ch1):
  //   row = (in + lb2)*8 + t8, chunk = lb1*4   (per p: in += 2 -> +16 rows)
  uint32_t kvoff = (uint32_t)(((lb2*8 + t8)*RSW) + lb1*4)*4;
  uint32_t kbase = smem_base + (uint32_t)Q_WORDS*4 + kvoff;
  uint32_t vbase = smem_base + (uint32_t)(Q_WORDS + 2*K_WORDS)*4 + kvoff;
  constexpr uint32_t PSTRIDE = 16*RSW*4;   // 2 key/d groups = 16 rows
  constexpr uint32_t KBUF = K_WORDS*4, VBUF = V_WORDS*4;

  // Q tile: 128 rows x 64 halves (128B/row -> 8 cpa16 chunks/row)
  #pragma unroll
  for(int j=0;j<4;j++){
    int idx = tid + j*256;
    int r = idx>>3, c = idx&7;
    cpa16((char*)(Qw + r*RSW) + c*16, Qg + (size_t)r*HD_ + c*8);
  }
  cpa_commit();

  auto loadKV = [&](int buf, int it){
    const __half* kg = Kg + (size_t)it*FN*HD_;
    const __half* vg = Vg + it*FN;          // V^T: column offset
    #pragma unroll
    for(int j=0;j<2;j++){                   // K: 64 rows x 64 halves
      int idx = tid + j*256;
      int r = idx>>3, c = idx&7;
      cpa16((char*)(Kw + buf*K_WORDS + r*RSW) + c*16, kg + (size_t)r*HD_ + c*8);
    }
    #pragma unroll
    for(int j=0;j<2;j++){                   // V^T: 64 d-rows x 64 keys
      int idx = tid + j*256;
      int r = idx>>3, c = idx&7;
      cpa16((char*)(Vw + buf*V_WORDS + r*RSW) + c*16, vg + (size_t)r*L_ + c*8);
    }
    if(tid < 16) cpa16(&Ms[buf*FN + tid*4], mg + it*FN + tid*4);
  };

  loadKV(0,0); cpa_commit();

  float o[8][4];
  #pragma unroll
  for(int i=0;i<8;i++)
    #pragma unroll
    for(int j=0;j<4;j++) o[i][j]=0.f;
  float mo0=-1e30f, mo1=-1e30f, lo0=0.f, lo1=0.f;

  #pragma unroll 1
  for(int it=0; it<L_/FN; it++){
    int buf = it&1;
    if(it+1 < L_/FN){ loadKV(buf^1, it+1); cpa_commit(); cpa_wait<1>(); }
    else            { cpa_wait<0>(); }
    __syncthreads();

    uint32_t kab = kbase + buf*KBUF;
    uint32_t vab = vbase + buf*VBUF;
    const int* ms = Ms + buf*FN;

    // S = Q @ K^T : 4 k16 steps over HD=64 (Q pre-scaled by 1/sqrt(HD))
    float s[8][4];
    #pragma unroll
    for(int i=0;i<8;i++)
      #pragma unroll
      for(int j=0;j<4;j++) s[i][j]=0.f;

    #pragma unroll
    for(int kk=0; kk<4; kk++){
      uint32_t af[4];
      ldsm4(af[0],af[1],af[2],af[3], qaddr + kk*32);
      #pragma unroll
      for(int p=0;p<4;p++){
        uint32_t b0,b1,b2,b3;
        ldsm4(b0,b1,b2,b3, kab + p*PSTRIDE + kk*32);
        uint32_t bfa[2] = {b0,b1}, bfb[2] = {b2,b3};
        mma_f16(s[2*p  ], af, bfa);
        mma_f16(s[2*p+1], af, bfb);
      }
    }

    // mask
    #pragma unroll
    for(int in=0;in<8;in++){
      int c0 = in*8 + tg*2;
      bool ok0 = ms[c0]!=0, ok1 = ms[c0+1]!=0;
      s[in][0] = ok0 ? s[in][0] : -1e30f;
      s[in][1] = ok1 ? s[in][1] : -1e30f;
      s[in][2] = ok0 ? s[in][2] : -1e30f;
      s[in][3] = ok1 ? s[in][3] : -1e30f;
    }

    // online softmax; rows (w*16+g) and (+8) live within one quad
    float mx0=-1e30f, mx1=-1e30f;
    #pragma unroll
    for(int in=0;in<8;in++){
      mx0 = fmaxf(mx0, fmaxf(s[in][0], s[in][1]));
      mx1 = fmaxf(mx1, fmaxf(s[in][2], s[in][3]));
    }
    mx0 = fmaxf(mx0, __shfl_xor_sync(0xffffffffu, mx0, 1));
    mx0 = fmaxf(mx0, __shfl_xor_sync(0xffffffffu, mx0, 2));
    mx1 = fmaxf(mx1, __shfl_xor_sync(0xffffffffu, mx1, 1));
    mx1 = fmaxf(mx1, __shfl_xor_sync(0xffffffffu, mx1, 2));

    float mn0 = fmaxf(mo0, mx0), mn1 = fmaxf(mo1, mx1);
    float sc0 = __expf(mo0 - mn0), sc1 = __expf(mo1 - mn1);

    float rs0=0.f, rs1=0.f;
    #pragma unroll
    for(int in=0;in<8;in++){
      s[in][0] = __expf(s[in][0]-mn0); rs0 += s[in][0];
      s[in][1] = __expf(s[in][1]-mn0); rs0 += s[in][1];
      s[in][2] = __expf(s[in][2]-mn1); rs1 += s[in][2];
      s[in][3] = __expf(s[in][3]-mn1); rs1 += s[in][3];
    }
    rs0 += __shfl_xor_sync(0xffffffffu, rs0, 1);
    rs0 += __shfl_xor_sync(0xffffffffu, rs0, 2);
    rs1 += __shfl_xor_sync(0xffffffffu, rs1, 1);
    rs1 += __shfl_xor_sync(0xffffffffu, rs1, 2);

    lo0 = lo0*sc0 + rs0;
    lo1 = lo1*sc1 + rs1;
    mo0 = mn0; mo1 = mn1;

    #pragma unroll
    for(int in=0;in<8;in++){
      o[in][0]*=sc0; o[in][1]*=sc0; o[in][2]*=sc1; o[in][3]*=sc1;
    }

    // O += P @ V : S C-frags map directly onto fp16 k16 A-frags (no shuffles)
    #pragma unroll
    for(int kb=0;kb<4;kb++){
      uint32_t ap[4];
      ap[0] = h2u(__floats2half2_rn(s[2*kb  ][0], s[2*kb  ][1]));
      ap[1] = h2u(__floats2half2_rn(s[2*kb  ][2], s[2*kb  ][3]));
      ap[2] = h2u(__floats2half2_rn(s[2*kb+1][0], s[2*kb+1][1]));
      ap[3] = h2u(__floats2half2_rn(s[2*kb+1][2], s[2*kb+1][3]));
      #pragma unroll
      for(int p=0;p<4;p++){
        uint32_t b0,b1,b2,b3;
        ldsm4(b0,b1,b2,b3, vab + p*PSTRIDE + kb*32);
        uint32_t bfa[2] = {b0,b1}, bfb[2] = {b2,b3};
        mma_f16(o[2*p  ], ap, bfa);
        mma_f16(o[2*p+1], ap, bfb);
      }
    }
    __syncthreads();
  }

  float inv0 = 1.f/lo0, inv1 = 1.f/lo1;
  int r0 = q0 + rb + g;
  float* op0 = g_ctx + (size_t)(b*L_ + r0    )*D_ + (bh&7)*HD_;
  float* op1 = g_ctx + (size_t)(b*L_ + r0 + 8)*D_ + (bh&7)*HD_;
  #pragma unroll
  for(int in=0;in<8;in++){
    int d = in*8 + tg*2;
    *(float2*)(op0 + d) = make_float2(o[in][0]*inv0, o[in][1]*inv0);
    *(float2*)(op1 + d) = make_float2(o[in][2]*inv1, o[in][3]*inv1);
  }
}

// ---------------------------------------------------------------------------
extern "C" void kernel_launch(void* const* d_in, const int* in_sizes, int n_in,
                              void* d_out, int out_size)
{
  (void)in_sizes; (void)n_in; (void)out_size;
  const float* query = (const float*)d_in[0];
  const float* key   = (const float*)d_in[1];
  const float* value = (const float*)d_in[2];
  const int*   mask  = (const int*)d_in[3];
  const float* Wq = (const float*)d_in[4];
  const float* bq = (const float*)d_in[5];
  const float* Wk = (const float*)d_in[6];
  const float* bk = (const float*)d_in[7];
  const float* Wv = (const float*)d_in[8];
  const float* bv = (const float*)d_in[9];
  const float* Wo = (const float*)d_in[10];
  const float* bo = (const float*)d_in[11];
  float* out = (float*)d_out;

  static bool attr_done = false;
  if(!attr_done){
    cudaFuncSetAttribute(gemm_tf32,  cudaFuncAttributeMaxDynamicSharedMemorySize, GEMM_SMEM);
    cudaFuncSetAttribute(flash_attn, cudaFuncAttributeMaxDynamicSharedMemorySize, FLASH_SMEM);
    attr_done = true;
  }

  dim3 gg(D_/BN, M_/BM);            // (4, 64)
  gemm_tf32<<<gg, 256, GEMM_SMEM>>>(query, Wq, bq, nullptr, 1);
  gemm_tf32<<<gg, 256, GEMM_SMEM>>>(key,   Wk, bk, nullptr, 2);
  gemm_tf32<<<gg, 256, GEMM_SMEM>>>(value, Wv, bv, nullptr, 3);

  dim3 fg(L_/FM, B_*H_);            // (32, 16)
  flash_attn<<<fg, 256, FLASH_SMEM>>>(mask);

  gemm_tf32<<<gg, 256, GEMM_SMEM>>>(nullptr, Wo, bo, out, 4);
}

// round 7
// speedup vs baseline: 2.0788x; 1.0841x over previous
#include <cuda_runtime.h>
#include <cuda_fp16.h>
#include <cstdint>

#define DEVI __device__ __forceinline__

constexpr int B_  = 2;
constexpr int L_  = 4096;
constexpr int D_  = 512;
constexpr int H_  = 8;
constexpr int HD_ = 64;
constexpr int M_  = B_ * L_;   // 8192

// scratch: __device__ globals (allocation-free rule)
__device__ __half g_qh[B_*H_*L_*HD_];   // [b,h,l,d] (pre-scaled by 0.125*log2e)
__device__ __half g_kh[B_*H_*L_*HD_];   // [b,h,l,d]
__device__ __half g_vt[B_*H_*HD_*L_];   // [b,h,d,l]  (transposed)
__device__ float  g_ctx[M_*D_];

DEVI uint32_t f2tf32(float x){ uint32_t r; asm("cvt.rna.tf32.f32 %0, %1;":"=r"(r):"f"(x)); return r; }
DEVI uint32_t h2u(__half2 h){ union{ __half2 h; uint32_t u; } c; c.h = h; return c.u; }

DEVI void mma_tf32(float* c, const uint32_t* a, const uint32_t* b){
  asm volatile("mma.sync.aligned.m16n8k8.row.col.f32.tf32.tf32.f32 "
    "{%0,%1,%2,%3},{%4,%5,%6,%7},{%8,%9},{%0,%1,%2,%3};\n"
    : "+f"(c[0]),"+f"(c[1]),"+f"(c[2]),"+f"(c[3])
    : "r"(a[0]),"r"(a[1]),"r"(a[2]),"r"(a[3]),"r"(b[0]),"r"(b[1]));
}

DEVI void mma_f16(float* c, const uint32_t* a, const uint32_t* b){
  asm volatile("mma.sync.aligned.m16n8k16.row.col.f32.f16.f16.f32 "
    "{%0,%1,%2,%3},{%4,%5,%6,%7},{%8,%9},{%0,%1,%2,%3};\n"
    : "+f"(c[0]),"+f"(c[1]),"+f"(c[2]),"+f"(c[3])
    : "r"(a[0]),"r"(a[1]),"r"(a[2]),"r"(a[3]),"r"(b[0]),"r"(b[1]));
}

DEVI void ldsm4(uint32_t& r0, uint32_t& r1, uint32_t& r2, uint32_t& r3, uint32_t addr){
  asm volatile("ldmatrix.sync.aligned.m8n8.x4.shared.b16 {%0,%1,%2,%3}, [%4];"
    : "=r"(r0),"=r"(r1),"=r"(r2),"=r"(r3) : "r"(addr));
}

DEVI void cpa16(void* s, const void* g){
  uint32_t sa = (uint32_t)__cvta_generic_to_shared(s);
  asm volatile("cp.async.cg.shared.global [%0], [%1], 16;\n"::"r"(sa),"l"(g));
}
DEVI void cpa_commit(){ asm volatile("cp.async.commit_group;\n"); }
template<int N> DEVI void cpa_wait(){ asm volatile("cp.async.wait_group %0;\n"::"n"(N)); }

// ---------------------------------------------------------------------------
// TF32 GEMM: C[M,512] = A[M,512] @ W[512,512] + bias
// mode 4: A = g_ctx, plain f32 out.  mode 1/2: fp16 scatter to g_qh/g_kh
// (mode 1 additionally scales by 0.125*log2e for exp2-domain softmax).
// mode 3: fp16 transposed scatter to g_vt.
// ---------------------------------------------------------------------------
constexpr int BM = 128, BN = 128, BK = 32;
constexpr int AST = BK + 4;    // 36
constexpr int BST = BN + 8;    // 136
constexpr int GEMM_SMEM = (2*BM*AST + 2*BK*BST) * 4;

__global__ void __launch_bounds__(256,2) gemm_tf32(
  const float* __restrict__ Ain, const float* __restrict__ W,
  const float* __restrict__ bias, float* __restrict__ Cplain, int mode)
{
  extern __shared__ float sm[];
  float* As = sm;                  // [2][BM][AST]
  float* Bs = sm + 2*BM*AST;       // [2][BK][BST]
  const float* A = (mode==4) ? g_ctx : Ain;

  int tid = threadIdx.x;
  int m0 = blockIdx.y*BM, n0 = blockIdx.x*BN;
  int w = tid>>5, lane = tid&31, g = lane>>2, tg = lane&3;
  int wm = (w>>1)*32, wn = (w&1)*64;

  const float* gA = A + (size_t)m0*D_;
  const float* gB = W + n0;

  float acc[2][8][4];
  #pragma unroll
  for(int i=0;i<2;i++)
    #pragma unroll
    for(int j=0;j<8;j++)
      #pragma unroll
      for(int k=0;k<4;k++) acc[i][j][k]=0.f;

  auto load_tiles = [&](int buf, int kt){
    #pragma unroll
    for(int j=0;j<4;j++){                       // A: 128x32
      int idx = tid + j*256;
      int r = idx>>3, c4 = idx&7;
      cpa16(&As[buf*BM*AST + r*AST + c4*4], gA + (size_t)r*D_ + kt*BK + c4*4);
    }
    #pragma unroll
    for(int j=0;j<4;j++){                       // B: 32x128
      int idx = tid + j*256;
      int r = idx>>5, c4 = idx&31;
      cpa16(&Bs[buf*BK*BST + r*BST + c4*4], gB + (size_t)(kt*BK + r)*D_ + c4*4);
    }
  };

  load_tiles(0,0); cpa_commit();

  #pragma unroll 1
  for(int kt=0; kt<D_/BK; kt++){
    if(kt+1 < D_/BK){ load_tiles((kt+1)&1, kt+1); cpa_commit(); cpa_wait<1>(); }
    else            { cpa_wait<0>(); }
    __syncthreads();
    const float* as = As + (kt&1)*BM*AST;
    const float* bs = Bs + (kt&1)*BK*BST;
    #pragma unroll
    for(int kk=0; kk<BK; kk+=8){
      uint32_t af[2][4], bf[8][2];
      #pragma unroll
      for(int im=0;im<2;im++){
        int rb = wm + im*16;
        af[im][0] = f2tf32(as[(rb+g  )*AST + kk+tg  ]);
        af[im][1] = f2tf32(as[(rb+g+8)*AST + kk+tg  ]);
        af[im][2] = f2tf32(as[(rb+g  )*AST + kk+tg+4]);
        af[im][3] = f2tf32(as[(rb+g+8)*AST + kk+tg+4]);
      }
      #pragma unroll
      for(int in=0;in<8;in++){
        int cb = wn + in*8 + g;
        bf[in][0] = f2tf32(bs[(kk+tg  )*BST + cb]);
        bf[in][1] = f2tf32(bs[(kk+tg+4)*BST + cb]);
      }
      #pragma unroll
      for(int im=0;im<2;im++)
        #pragma unroll
        for(int in=0;in<8;in++)
          mma_tf32(acc[im][in], af[im], bf[in]);
    }
    __syncthreads();
  }

  float oscale = (mode==1) ? 0.125f*1.44269504f : 1.0f;
  #pragma unroll
  for(int im=0;im<2;im++){
    int r0 = m0 + wm + im*16 + g;
    int r8 = r0 + 8;
    #pragma unroll
    for(int in=0;in<8;in++){
      int col = n0 + wn + in*8 + tg*2;
      float bx = bias[col], by = bias[col+1];
      float2 v0 = make_float2(acc[im][in][0]+bx, acc[im][in][1]+by);
      float2 v1 = make_float2(acc[im][in][2]+bx, acc[im][in][3]+by);
      if(mode==4){
        *(float2*)(Cplain + (size_t)r0*D_ + col) = v0;
        *(float2*)(Cplain + (size_t)r8*D_ + col) = v1;
      } else {
        int h = col>>6, d = col&63;
        int b0i = r0>>12, t0 = r0&4095;
        int b1i = r8>>12, t1 = r8&4095;
        if(mode==3){
          // V transposed: [b,h,d,l]
          size_t i0 = ((size_t)(b0i*H_ + h)*HD_ + d)*L_ + t0;
          size_t i1 = ((size_t)(b1i*H_ + h)*HD_ + d)*L_ + t1;
          g_vt[i0]      = __float2half_rn(v0.x);
          g_vt[i0 + L_] = __float2half_rn(v0.y);
          g_vt[i1]      = __float2half_rn(v1.x);
          g_vt[i1 + L_] = __float2half_rn(v1.y);
        } else {
          __half* C = (mode==1) ? g_qh : g_kh;
          size_t i0 = ((size_t)(b0i*H_ + h)*L_ + t0)*HD_ + d;
          size_t i1 = ((size_t)(b1i*H_ + h)*L_ + t1)*HD_ + d;
          *(__half2*)(C + i0) = __floats2half2_rn(v0.x*oscale, v0.y*oscale);
          *(__half2*)(C + i1) = __floats2half2_rn(v1.x*oscale, v1.y*oscale);
        }
      }
    }
  }
}

// ---------------------------------------------------------------------------
// Flash attention v3: 8 warps x 32 q-rows (FM=256), Q frags in registers,
// K/V fragments loaded once per warp and reused by both row-blocks.
// exp2-domain softmax (Q pre-scaled by 0.125*log2e).
// ---------------------------------------------------------------------------
constexpr int FM = 256, FN = 64;
constexpr int RSW = 36;                 // row stride in 32-bit words
constexpr int Q_WORDS = FM*RSW;         // 9216
constexpr int K_WORDS = FN*RSW;         // 2304
constexpr int V_WORDS = FN*RSW;         // 2304
constexpr int FLASH_SMEM = (Q_WORDS + 2*K_WORDS + 2*V_WORDS)*4 + 2*FN*4;

__global__ void __launch_bounds__(256,1) flash_attn(const int* __restrict__ mask)
{
  extern __shared__ uint32_t smw[];
  uint32_t* Qw = smw;                    // [256][36]
  uint32_t* Kw = smw + Q_WORDS;          // [2][64][36]
  uint32_t* Vw = Kw + 2*K_WORDS;         // [2][64][36]  (V^T: row=d, col=key)
  int*      Ms = (int*)(Vw + 2*V_WORDS);

  int tid = threadIdx.x, w = tid>>5, lane = tid&31, g = lane>>2, tg = lane&3;
  int bh = blockIdx.y;
  int b  = bh >> 3;
  int q0 = blockIdx.x * FM;
  int rb = w*32;

  const __half* Qg = g_qh + (size_t)bh*L_*HD_ + (size_t)q0*HD_;
  const __half* Kg = g_kh + (size_t)bh*L_*HD_;
  const __half* Vg = g_vt + (size_t)bh*HD_*L_;
  const int*    mg = mask + b*L_;

  // ---- LDSM per-thread addresses (bytes, shared address space) ----
  uint32_t smem_base = (uint32_t)__cvta_generic_to_shared(smw);
  int t8  = lane & 7;
  int lb1 = (lane>>3) & 1;
  int lb2 = lane>>4;
  // Q x4 frag for row-block at row r0: m0 rows r0..+7 ch0 | m1 r0+8 ch0 | m2 r0 ch1 | m3 r0+8 ch1
  uint32_t qaddr0 = smem_base + (uint32_t)((rb      + lb1*8 + t8)*RSW + lb2*4)*4;
  uint32_t qaddr1 = smem_base + (uint32_t)((rb + 16 + lb1*8 + t8)*RSW + lb2*4)*4;
  // K/V x4: (in,ch0),(in,ch1),(in+1,ch0),(in+1,ch1): row=(in+lb2)*8+t8, chunk=lb1*4
  uint32_t kvoff = (uint32_t)(((lb2*8 + t8)*RSW) + lb1*4)*4;
  uint32_t kbase = smem_base + (uint32_t)Q_WORDS*4 + kvoff;
  uint32_t vbase = smem_base + (uint32_t)(Q_WORDS + 2*K_WORDS)*4 + kvoff;
  constexpr uint32_t PSTRIDE = 16*RSW*4;   // 2 key/d groups = 16 rows
  constexpr uint32_t KBUF = K_WORDS*4, VBUF = V_WORDS*4;

  // Q tile: 256 rows x 64 halves (128B/row -> 8 cpa16 chunks/row)
  #pragma unroll
  for(int j=0;j<8;j++){
    int idx = tid + j*256;
    int r = idx>>3, c = idx&7;
    cpa16((char*)(Qw + r*RSW) + c*16, Qg + (size_t)r*HD_ + c*8);
  }
  cpa_commit();

  auto loadKV = [&](int buf, int it){
    const __half* kg = Kg + (size_t)it*FN*HD_;
    const __half* vg = Vg + it*FN;          // V^T: column offset
    #pragma unroll
    for(int j=0;j<2;j++){                   // K: 64 rows x 64 halves
      int idx = tid + j*256;
      int r = idx>>3, c = idx&7;
      cpa16((char*)(Kw + buf*K_WORDS + r*RSW) + c*16, kg + (size_t)r*HD_ + c*8);
    }
    #pragma unroll
    for(int j=0;j<2;j++){                   // V^T: 64 d-rows x 64 keys
      int idx = tid + j*256;
      int r = idx>>3, c = idx&7;
      cpa16((char*)(Vw + buf*V_WORDS + r*RSW) + c*16, vg + (size_t)r*L_ + c*8);
    }
    if(tid < 16) cpa16(&Ms[buf*FN + tid*4], mg + it*FN + tid*4);
  };

  // Q frags -> registers (loop-invariant). Wait for Q cp.async first.
  cpa_wait<0>();
  __syncthreads();
  uint32_t qf[2][4][4];
  #pragma unroll
  for(int kk=0;kk<4;kk++){
    ldsm4(qf[0][kk][0],qf[0][kk][1],qf[0][kk][2],qf[0][kk][3], qaddr0 + kk*32);
    ldsm4(qf[1][kk][0],qf[1][kk][1],qf[1][kk][2],qf[1][kk][3], qaddr1 + kk*32);
  }

  loadKV(0,0); cpa_commit();

  float o[2][8][4];
  #pragma unroll
  for(int m=0;m<2;m++)
    #pragma unroll
    for(int i=0;i<8;i++)
      #pragma unroll
      for(int j=0;j<4;j++) o[m][i][j]=0.f;
  float mo[4] = {-1e30f,-1e30f,-1e30f,-1e30f};
  float lo[4] = {0.f,0.f,0.f,0.f};

  #pragma unroll 1
  for(int it=0; it<L_/FN; it++){
    int buf = it&1;
    if(it+1 < L_/FN){ loadKV(buf^1, it+1); cpa_commit(); cpa_wait<1>(); }
    else            { cpa_wait<0>(); }
    __syncthreads();

    uint32_t kab = kbase + buf*KBUF;
    uint32_t vab = vbase + buf*VBUF;
    const int* ms = Ms + buf*FN;

    // S = Q @ K^T for both row-blocks; K frags loaded once per kk
    float s[2][8][4];
    #pragma unroll
    for(int m=0;m<2;m++)
      #pragma unroll
      for(int i=0;i<8;i++)
        #pragma unroll
        for(int j=0;j<4;j++) s[m][i][j]=0.f;

    #pragma unroll
    for(int kk=0; kk<4; kk++){
      #pragma unroll
      for(int p=0;p<4;p++){
        uint32_t b0,b1,b2,b3;
        ldsm4(b0,b1,b2,b3, kab + p*PSTRIDE + kk*32);
        uint32_t bfa[2] = {b0,b1}, bfb[2] = {b2,b3};
        mma_f16(s[0][2*p  ], qf[0][kk], bfa);
        mma_f16(s[0][2*p+1], qf[0][kk], bfb);
        mma_f16(s[1][2*p  ], qf[1][kk], bfa);
        mma_f16(s[1][2*p+1], qf[1][kk], bfb);
      }
    }

    // mask + online softmax (exp2 domain) per row-block
    #pragma unroll
    for(int m=0;m<2;m++){
      #pragma unroll
      for(int in=0;in<8;in++){
        int c0 = in*8 + tg*2;
        bool ok0 = ms[c0]!=0, ok1 = ms[c0+1]!=0;
        s[m][in][0] = ok0 ? s[m][in][0] : -1e30f;
        s[m][in][1] = ok1 ? s[m][in][1] : -1e30f;
        s[m][in][2] = ok0 ? s[m][in][2] : -1e30f;
        s[m][in][3] = ok1 ? s[m][in][3] : -1e30f;
      }
      float mx0=-1e30f, mx1=-1e30f;
      #pragma unroll
      for(int in=0;in<8;in++){
        mx0 = fmaxf(mx0, fmaxf(s[m][in][0], s[m][in][1]));
        mx1 = fmaxf(mx1, fmaxf(s[m][in][2], s[m][in][3]));
      }
      mx0 = fmaxf(mx0, __shfl_xor_sync(0xffffffffu, mx0, 1));
      mx0 = fmaxf(mx0, __shfl_xor_sync(0xffffffffu, mx0, 2));
      mx1 = fmaxf(mx1, __shfl_xor_sync(0xffffffffu, mx1, 1));
      mx1 = fmaxf(mx1, __shfl_xor_sync(0xffffffffu, mx1, 2));

      float mn0 = fmaxf(mo[2*m], mx0), mn1 = fmaxf(mo[2*m+1], mx1);
      float sc0 = exp2f(mo[2*m] - mn0), sc1 = exp2f(mo[2*m+1] - mn1);

      float rs0=0.f, rs1=0.f;
      #pragma unroll
      for(int in=0;in<8;in++){
        s[m][in][0] = exp2f(s[m][in][0]-mn0); rs0 += s[m][in][0];
        s[m][in][1] = exp2f(s[m][in][1]-mn0); rs0 += s[m][in][1];
        s[m][in][2] = exp2f(s[m][in][2]-mn1); rs1 += s[m][in][2];
        s[m][in][3] = exp2f(s[m][in][3]-mn1); rs1 += s[m][in][3];
      }
      rs0 += __shfl_xor_sync(0xffffffffu, rs0, 1);
      rs0 += __shfl_xor_sync(0xffffffffu, rs0, 2);
      rs1 += __shfl_xor_sync(0xffffffffu, rs1, 1);
      rs1 += __shfl_xor_sync(0xffffffffu, rs1, 2);

      lo[2*m]   = lo[2*m]*sc0 + rs0;
      lo[2*m+1] = lo[2*m+1]*sc1 + rs1;
      mo[2*m] = mn0; mo[2*m+1] = mn1;

      #pragma unroll
      for(int in=0;in<8;in++){
        o[m][in][0]*=sc0; o[m][in][1]*=sc0; o[m][in][2]*=sc1; o[m][in][3]*=sc1;
      }
    }

    // O += P @ V ; V frags loaded once per kb, used by both row-blocks
    #pragma unroll
    for(int kb=0;kb<4;kb++){
      uint32_t ap0[4], ap1[4];
      ap0[0] = h2u(__floats2half2_rn(s[0][2*kb  ][0], s[0][2*kb  ][1]));
      ap0[1] = h2u(__floats2half2_rn(s[0][2*kb  ][2], s[0][2*kb  ][3]));
      ap0[2] = h2u(__floats2half2_rn(s[0][2*kb+1][0], s[0][2*kb+1][1]));
      ap0[3] = h2u(__floats2half2_rn(s[0][2*kb+1][2], s[0][2*kb+1][3]));
      ap1[0] = h2u(__floats2half2_rn(s[1][2*kb  ][0], s[1][2*kb  ][1]));
      ap1[1] = h2u(__floats2half2_rn(s[1][2*kb  ][2], s[1][2*kb  ][3]));
      ap1[2] = h2u(__floats2half2_rn(s[1][2*kb+1][0], s[1][2*kb+1][1]));
      ap1[3] = h2u(__floats2half2_rn(s[1][2*kb+1][2], s[1][2*kb+1][3]));
      #pragma unroll
      for(int p=0;p<4;p++){
        uint32_t b0,b1,b2,b3;
        ldsm4(b0,b1,b2,b3, vab + p*PSTRIDE + kb*32);
        uint32_t bfa[2] = {b0,b1}, bfb[2] = {b2,b3};
        mma_f16(o[0][2*p  ], ap0, bfa);
        mma_f16(o[0][2*p+1], ap0, bfb);
        mma_f16(o[1][2*p  ], ap1, bfa);
        mma_f16(o[1][2*p+1], ap1, bfb);
      }
    }
    __syncthreads();
  }

  #pragma unroll
  for(int m=0;m<2;m++){
    float inv0 = 1.f/lo[2*m], inv1 = 1.f/lo[2*m+1];
    int r0 = q0 + rb + m*16 + g;
    float* op0 = g_ctx + (size_t)(b*L_ + r0    )*D_ + (bh&7)*HD_;
    float* op1 = g_ctx + (size_t)(b*L_ + r0 + 8)*D_ + (bh&7)*HD_;
    #pragma unroll
    for(int in=0;in<8;in++){
      int d = in*8 + tg*2;
      *(float2*)(op0 + d) = make_float2(o[m][in][0]*inv0, o[m][in][1]*inv0);
      *(float2*)(op1 + d) = make_float2(o[m][in][2]*inv1, o[m][in][3]*inv1);
    }
  }
}

// ---------------------------------------------------------------------------
extern "C" void kernel_launch(void* const* d_in, const int* in_sizes, int n_in,
                              void* d_out, int out_size)
{
  (void)in_sizes; (void)n_in; (void)out_size;
  const float* query = (const float*)d_in[0];
  const float* key   = (const float*)d_in[1];
  const float* value = (const float*)d_in[2];
  const int*   mask  = (const int*)d_in[3];
  const float* Wq = (const float*)d_in[4];
  const float* bq = (const float*)d_in[5];
  const float* Wk = (const float*)d_in[6];
  const float* bk = (const float*)d_in[7];
  const float* Wv = (const float*)d_in[8];
  const float* bv = (const float*)d_in[9];
  const float* Wo = (const float*)d_in[10];
  const float* bo = (const float*)d_in[11];
  float* out = (float*)d_out;

  static bool attr_done = false;
  if(!attr_done){
    cudaFuncSetAttribute(gemm_tf32,  cudaFuncAttributeMaxDynamicSharedMemorySize, GEMM_SMEM);
    cudaFuncSetAttribute(flash_attn, cudaFuncAttributeMaxDynamicSharedMemorySize, FLASH_SMEM);
    attr_done = true;
  }

  dim3 gg(D_/BN, M_/BM);            // (4, 64)
  gemm_tf32<<<gg, 256, GEMM_SMEM>>>(query, Wq, bq, nullptr, 1);
  gemm_tf32<<<gg, 256, GEMM_SMEM>>>(key,   Wk, bk, nullptr, 2);
  gemm_tf32<<<gg, 256, GEMM_SMEM>>>(value, Wv, bv, nullptr, 3);

  dim3 fg(L_/FM, B_*H_);            // (16, 16)
  flash_attn<<<fg, 256, FLASH_SMEM>>>(mask);

  gemm_tf32<<<gg, 256, GEMM_SMEM>>>(nullptr, Wo, bo, out, 4);
}

// round 8
// speedup vs baseline: 2.4537x; 1.1803x over previous
#include <cuda_runtime.h>
#include <cuda_fp16.h>
#include <cstdint>

#define DEVI __device__ __forceinline__

constexpr int B_  = 2;
constexpr int L_  = 4096;
constexpr int D_  = 512;
constexpr int H_  = 8;
constexpr int HD_ = 64;
constexpr int M_  = B_ * L_;          // 8192
constexpr size_t MD = (size_t)M_*D_;  // 4194304
constexpr size_t DD = (size_t)D_*D_;  // 262144

// scratch: __device__ globals (allocation-free rule)
__device__ __half g_x16[3*MD];          // fp16 copies of query,key,value
__device__ __half g_w16[4*DD];          // fp16 copies of Wq,Wk,Wv,Wo
__device__ __half g_qh[B_*H_*L_*HD_];   // [b,h,l,d] (pre-scaled by 0.125*log2e)
__device__ __half g_kh[B_*H_*L_*HD_];   // [b,h,l,d]
__device__ __half g_vt[B_*H_*HD_*L_];   // [b,h,d,l]  (transposed)
__device__ __half g_ctx16[MD];          // attention output, fp16

DEVI uint32_t h2u(__half2 h){ union{ __half2 h; uint32_t u; } c; c.h = h; return c.u; }

DEVI void mma_f16(float* c, const uint32_t* a, const uint32_t* b){
  asm volatile("mma.sync.aligned.m16n8k16.row.col.f32.f16.f16.f32 "
    "{%0,%1,%2,%3},{%4,%5,%6,%7},{%8,%9},{%0,%1,%2,%3};\n"
    : "+f"(c[0]),"+f"(c[1]),"+f"(c[2]),"+f"(c[3])
    : "r"(a[0]),"r"(a[1]),"r"(a[2]),"r"(a[3]),"r"(b[0]),"r"(b[1]));
}

DEVI void ldsm4(uint32_t& r0, uint32_t& r1, uint32_t& r2, uint32_t& r3, uint32_t addr){
  asm volatile("ldmatrix.sync.aligned.m8n8.x4.shared.b16 {%0,%1,%2,%3}, [%4];"
    : "=r"(r0),"=r"(r1),"=r"(r2),"=r"(r3) : "r"(addr));
}
DEVI void ldsm4t(uint32_t& r0, uint32_t& r1, uint32_t& r2, uint32_t& r3, uint32_t addr){
  asm volatile("ldmatrix.sync.aligned.m8n8.x4.trans.shared.b16 {%0,%1,%2,%3}, [%4];"
    : "=r"(r0),"=r"(r1),"=r"(r2),"=r"(r3) : "r"(addr));
}

DEVI void cpa16(void* s, const void* g){
  uint32_t sa = (uint32_t)__cvta_generic_to_shared(s);
  asm volatile("cp.async.cg.shared.global [%0], [%1], 16;\n"::"r"(sa),"l"(g));
}
DEVI void cpa_commit(){ asm volatile("cp.async.commit_group;\n"); }
template<int N> DEVI void cpa_wait(){ asm volatile("cp.async.wait_group %0;\n"::"n"(N)); }

// ---------------------------------------------------------------------------
// conv16: round inputs + weights to fp16 once (RN — same mantissa as TF32)
// ---------------------------------------------------------------------------
__global__ void conv16(const float* __restrict__ q, const float* __restrict__ k,
                       const float* __restrict__ v,
                       const float* __restrict__ wq, const float* __restrict__ wk,
                       const float* __restrict__ wv, const float* __restrict__ wo)
{
  size_t i = ((size_t)blockIdx.x*blockDim.x + threadIdx.x)*4;
  if(i < MD){
    float4 a;
    a = *(const float4*)(q+i);
    *(__half2*)(g_x16 + i)        = __floats2half2_rn(a.x,a.y);
    *(__half2*)(g_x16 + i + 2)    = __floats2half2_rn(a.z,a.w);
    a = *(const float4*)(k+i);
    *(__half2*)(g_x16 + MD + i)   = __floats2half2_rn(a.x,a.y);
    *(__half2*)(g_x16 + MD + i+2) = __floats2half2_rn(a.z,a.w);
    a = *(const float4*)(v+i);
    *(__half2*)(g_x16 + 2*MD + i)   = __floats2half2_rn(a.x,a.y);
    *(__half2*)(g_x16 + 2*MD + i+2) = __floats2half2_rn(a.z,a.w);
  }
  if(i < DD){
    float4 a;
    a = *(const float4*)(wq+i);
    *(__half2*)(g_w16 + i)        = __floats2half2_rn(a.x,a.y);
    *(__half2*)(g_w16 + i + 2)    = __floats2half2_rn(a.z,a.w);
    a = *(const float4*)(wk+i);
    *(__half2*)(g_w16 + DD + i)   = __floats2half2_rn(a.x,a.y);
    *(__half2*)(g_w16 + DD + i+2) = __floats2half2_rn(a.z,a.w);
    a = *(const float4*)(wv+i);
    *(__half2*)(g_w16 + 2*DD + i)   = __floats2half2_rn(a.x,a.y);
    *(__half2*)(g_w16 + 2*DD + i+2) = __floats2half2_rn(a.z,a.w);
    a = *(const float4*)(wo+i);
    *(__half2*)(g_w16 + 3*DD + i)   = __floats2half2_rn(a.x,a.y);
    *(__half2*)(g_w16 + 3*DD + i+2) = __floats2half2_rn(a.z,a.w);
  }
}

// ---------------------------------------------------------------------------
// fp16 GEMM: C[M,512] = A[M,512] @ W[512,512] + bias   (fp32 accum)
// mode = mode_base + blockIdx.z:
//   1/2: fp16 scatter to g_qh/g_kh (mode 1 scaled by 0.125*log2e)
//   3:   fp16 transposed scatter to g_vt
//   4:   A = g_ctx16, plain f32 out + bias
// ---------------------------------------------------------------------------
constexpr int GBM = 128, GBN = 128, GBK = 64;
constexpr int GAW = 36;   // A row stride (words); 72 halves
constexpr int GBW = 68;   // B row stride (words); 136 halves
constexpr int GA_WORDS = GBM*GAW;   // 4608
constexpr int GB_WORDS = GBK*GBW;   // 4352
constexpr int GEMM16_SMEM = (2*GA_WORDS + 2*GB_WORDS)*4;   // 71680

__global__ void __launch_bounds__(256,2) gemm_f16(
  const float* __restrict__ bq, const float* __restrict__ bk,
  const float* __restrict__ bv, const float* __restrict__ bo,
  float* __restrict__ out, int mode_base)
{
  extern __shared__ uint32_t smw[];
  uint32_t* Aw = smw;                    // [2][128][36]
  uint32_t* Bw = smw + 2*GA_WORDS;       // [2][64][68]

  int mode = mode_base + blockIdx.z;     // 1..3 or 4
  const __half* A = (mode==4) ? g_ctx16 : g_x16 + (size_t)(mode-1)*MD;
  const __half* W = g_w16 + (size_t)(mode-1)*DD;
  const float* bias = (mode==1)?bq : (mode==2)?bk : (mode==3)?bv : bo;

  int tid = threadIdx.x;
  int m0 = blockIdx.y*GBM, n0 = blockIdx.x*GBN;
  int w = tid>>5, lane = tid&31, g = lane>>2, tg = lane&3;
  int wm = (w>>1)*32, wn = (w&1)*64;

  // ldsm addresses
  uint32_t sbase = (uint32_t)__cvta_generic_to_shared(smw);
  int t8  = lane & 7;
  int lb1 = (lane>>3) & 1;
  int lb2 = lane>>4;
  uint32_t a0 = sbase + (uint32_t)((wm      + lb1*8 + t8)*GAW + lb2*4)*4;
  uint32_t a1 = sbase + (uint32_t)((wm + 16 + lb1*8 + t8)*GAW + lb2*4)*4;
  uint32_t bb = sbase + (uint32_t)(2*GA_WORDS)*4
              + (uint32_t)((lb1*8 + t8)*GBW)*4 + (uint32_t)(wn + lb2*8)*2;
  constexpr uint32_t ABUF = GA_WORDS*4, BBUF = GB_WORDS*4;
  constexpr uint32_t BKSTEP = 16*GBW*4;

  float acc[2][8][4];
  #pragma unroll
  for(int i=0;i<2;i++)
    #pragma unroll
    for(int j=0;j<8;j++)
      #pragma unroll
      for(int k2=0;k2<4;k2++) acc[i][j][k2]=0.f;

  auto load_tiles = [&](int buf, int kt){
    const __half* ga = A + (size_t)m0*D_ + kt*GBK;
    #pragma unroll
    for(int j=0;j<4;j++){                       // A: 128 rows x 64 halves (8 chunks)
      int idx = tid + j*256;
      int r = idx>>3, c = idx&7;
      cpa16((char*)(Aw + buf*GA_WORDS + r*GAW) + c*16, ga + (size_t)r*D_ + c*8);
    }
    const __half* gb = W + (size_t)(kt*GBK)*D_ + n0;
    #pragma unroll
    for(int j=0;j<4;j++){                       // B: 64 rows x 128 halves (16 chunks)
      int idx = tid + j*256;
      int r = idx>>4, c = idx&15;
      cpa16((char*)(Bw + buf*GB_WORDS + r*GBW) + c*16, gb + (size_t)r*D_ + c*8);
    }
  };

  load_tiles(0,0); cpa_commit();

  #pragma unroll 1
  for(int kt=0; kt<D_/GBK; kt++){
    if(kt+1 < D_/GBK){ load_tiles((kt+1)&1, kt+1); cpa_commit(); cpa_wait<1>(); }
    else             { cpa_wait<0>(); }
    __syncthreads();
    int buf = kt&1;
    uint32_t ac0 = a0 + buf*ABUF, ac1 = a1 + buf*ABUF;
    uint32_t bc  = bb + buf*BBUF;
    #pragma unroll
    for(int kk=0; kk<4; kk++){
      uint32_t af0[4], af1[4];
      ldsm4(af0[0],af0[1],af0[2],af0[3], ac0 + kk*32);
      ldsm4(af1[0],af1[1],af1[2],af1[3], ac1 + kk*32);
      #pragma unroll
      for(int j=0;j<4;j++){
        uint32_t b0,b1,b2,b3;
        ldsm4t(b0,b1,b2,b3, bc + kk*BKSTEP + j*32);
        uint32_t bfa[2] = {b0,b1}, bfb[2] = {b2,b3};
        mma_f16(acc[0][2*j  ], af0, bfa);
        mma_f16(acc[0][2*j+1], af0, bfb);
        mma_f16(acc[1][2*j  ], af1, bfa);
        mma_f16(acc[1][2*j+1], af1, bfb);
      }
    }
    __syncthreads();
  }

  float oscale = (mode==1) ? 0.125f*1.44269504f : 1.0f;
  #pragma unroll
  for(int im=0;im<2;im++){
    int r0 = m0 + wm + im*16 + g;
    int r8 = r0 + 8;
    #pragma unroll
    for(int in=0;in<8;in++){
      int col = n0 + wn + in*8 + tg*2;
      float bx = bias[col], by = bias[col+1];
      float2 v0 = make_float2(acc[im][in][0]+bx, acc[im][in][1]+by);
      float2 v1 = make_float2(acc[im][in][2]+bx, acc[im][in][3]+by);
      if(mode==4){
        *(float2*)(out + (size_t)r0*D_ + col) = v0;
        *(float2*)(out + (size_t)r8*D_ + col) = v1;
      } else {
        int h = col>>6, d = col&63;
        int b0i = r0>>12, t0 = r0&4095;
        int b1i = r8>>12, t1 = r8&4095;
        if(mode==3){
          // V transposed: [b,h,d,l]
          size_t i0 = ((size_t)(b0i*H_ + h)*HD_ + d)*L_ + t0;
          size_t i1 = ((size_t)(b1i*H_ + h)*HD_ + d)*L_ + t1;
          g_vt[i0]      = __float2half_rn(v0.x);
          g_vt[i0 + L_] = __float2half_rn(v0.y);
          g_vt[i1]      = __float2half_rn(v1.x);
          g_vt[i1 + L_] = __float2half_rn(v1.y);
        } else {
          __half* C = (mode==1) ? g_qh : g_kh;
          size_t i0 = ((size_t)(b0i*H_ + h)*L_ + t0)*HD_ + d;
          size_t i1 = ((size_t)(b1i*H_ + h)*L_ + t1)*HD_ + d;
          *(__half2*)(C + i0) = __floats2half2_rn(v0.x*oscale, v0.y*oscale);
          *(__half2*)(C + i1) = __floats2half2_rn(v1.x*oscale, v1.y*oscale);
        }
      }
    }
  }
}

// ---------------------------------------------------------------------------
// Flash attention: 8 warps x 32 q-rows (FM=256), Q frags in registers,
// K/V fragments loaded once per warp, reused by both row-blocks.
// exp2-domain softmax (Q pre-scaled by 0.125*log2e). Writes fp16 ctx.
// ---------------------------------------------------------------------------
constexpr int FM = 256, FN = 64;
constexpr int RSW = 36;                 // row stride in 32-bit words
constexpr int Q_WORDS = FM*RSW;         // 9216
constexpr int K_WORDS = FN*RSW;         // 2304
constexpr int V_WORDS = FN*RSW;         // 2304
constexpr int FLASH_SMEM = (Q_WORDS + 2*K_WORDS + 2*V_WORDS)*4 + 2*FN*4;

__global__ void __launch_bounds__(256,1) flash_attn(const int* __restrict__ mask)
{
  extern __shared__ uint32_t smw[];
  uint32_t* Qw = smw;                    // [256][36]
  uint32_t* Kw = smw + Q_WORDS;          // [2][64][36]
  uint32_t* Vw = Kw + 2*K_WORDS;         // [2][64][36]  (V^T: row=d, col=key)
  int*      Ms = (int*)(Vw + 2*V_WORDS);

  int tid = threadIdx.x, w = tid>>5, lane = tid&31, g = lane>>2, tg = lane&3;
  int bh = blockIdx.y;
  int b  = bh >> 3;
  int q0 = blockIdx.x * FM;
  int rb = w*32;

  const __half* Qg = g_qh + (size_t)bh*L_*HD_ + (size_t)q0*HD_;
  const __half* Kg = g_kh + (size_t)bh*L_*HD_;
  const __half* Vg = g_vt + (size_t)bh*HD_*L_;
  const int*    mg = mask + b*L_;

  uint32_t smem_base = (uint32_t)__cvta_generic_to_shared(smw);
  int t8  = lane & 7;
  int lb1 = (lane>>3) & 1;
  int lb2 = lane>>4;
  uint32_t qaddr0 = smem_base + (uint32_t)((rb      + lb1*8 + t8)*RSW + lb2*4)*4;
  uint32_t qaddr1 = smem_base + (uint32_t)((rb + 16 + lb1*8 + t8)*RSW + lb2*4)*4;
  uint32_t kvoff = (uint32_t)(((lb2*8 + t8)*RSW) + lb1*4)*4;
  uint32_t kbase = smem_base + (uint32_t)Q_WORDS*4 + kvoff;
  uint32_t vbase = smem_base + (uint32_t)(Q_WORDS + 2*K_WORDS)*4 + kvoff;
  constexpr uint32_t PSTRIDE = 16*RSW*4;
  constexpr uint32_t KBUF = K_WORDS*4, VBUF = V_WORDS*4;

  #pragma unroll
  for(int j=0;j<8;j++){
    int idx = tid + j*256;
    int r = idx>>3, c = idx&7;
    cpa16((char*)(Qw + r*RSW) + c*16, Qg + (size_t)r*HD_ + c*8);
  }
  cpa_commit();

  auto loadKV = [&](int buf, int it){
    const __half* kg = Kg + (size_t)it*FN*HD_;
    const __half* vg = Vg + it*FN;
    #pragma unroll
    for(int j=0;j<2;j++){
      int idx = tid + j*256;
      int r = idx>>3, c = idx&7;
      cpa16((char*)(Kw + buf*K_WORDS + r*RSW) + c*16, kg + (size_t)r*HD_ + c*8);
    }
    #pragma unroll
    for(int j=0;j<2;j++){
      int idx = tid + j*256;
      int r = idx>>3, c = idx&7;
      cpa16((char*)(Vw + buf*V_WORDS + r*RSW) + c*16, vg + (size_t)r*L_ + c*8);
    }
    if(tid < 16) cpa16(&Ms[buf*FN + tid*4], mg + it*FN + tid*4);
  };

  cpa_wait<0>();
  __syncthreads();
  uint32_t qf[2][4][4];
  #pragma unroll
  for(int kk=0;kk<4;kk++){
    ldsm4(qf[0][kk][0],qf[0][kk][1],qf[0][kk][2],qf[0][kk][3], qaddr0 + kk*32);
    ldsm4(qf[1][kk][0],qf[1][kk][1],qf[1][kk][2],qf[1][kk][3], qaddr1 + kk*32);
  }

  loadKV(0,0); cpa_commit();

  float o[2][8][4];
  #pragma unroll
  for(int m=0;m<2;m++)
    #pragma unroll
    for(int i=0;i<8;i++)
      #pragma unroll
      for(int j=0;j<4;j++) o[m][i][j]=0.f;
  float mo[4] = {-1e30f,-1e30f,-1e30f,-1e30f};
  float lo[4] = {0.f,0.f,0.f,0.f};

  #pragma unroll 1
  for(int it=0; it<L_/FN; it++){
    int buf = it&1;
    if(it+1 < L_/FN){ loadKV(buf^1, it+1); cpa_commit(); cpa_wait<1>(); }
    else            { cpa_wait<0>(); }
    __syncthreads();

    uint32_t kab = kbase + buf*KBUF;
    uint32_t vab = vbase + buf*VBUF;
    const int* ms = Ms + buf*FN;

    float s[2][8][4];
    #pragma unroll
    for(int m=0;m<2;m++)
      #pragma unroll
      for(int i=0;i<8;i++)
        #pragma unroll
        for(int j=0;j<4;j++) s[m][i][j]=0.f;

    #pragma unroll
    for(int kk=0; kk<4; kk++){
      #pragma unroll
      for(int p=0;p<4;p++){
        uint32_t b0,b1,b2,b3;
        ldsm4(b0,b1,b2,b3, kab + p*PSTRIDE + kk*32);
        uint32_t bfa[2] = {b0,b1}, bfb[2] = {b2,b3};
        mma_f16(s[0][2*p  ], qf[0][kk], bfa);
        mma_f16(s[0][2*p+1], qf[0][kk], bfb);
        mma_f16(s[1][2*p  ], qf[1][kk], bfa);
        mma_f16(s[1][2*p+1], qf[1][kk], bfb);
      }
    }

    #pragma unroll
    for(int m=0;m<2;m++){
      #pragma unroll
      for(int in=0;in<8;in++){
        int c0 = in*8 + tg*2;
        bool ok0 = ms[c0]!=0, ok1 = ms[c0+1]!=0;
        s[m][in][0] = ok0 ? s[m][in][0] : -1e30f;
        s[m][in][1] = ok1 ? s[m][in][1] : -1e30f;
        s[m][in][2] = ok0 ? s[m][in][2] : -1e30f;
        s[m][in][3] = ok1 ? s[m][in][3] : -1e30f;
      }
      float mx0=-1e30f, mx1=-1e30f;
      #pragma unroll
      for(int in=0;in<8;in++){
        mx0 = fmaxf(mx0, fmaxf(s[m][in][0], s[m][in][1]));
        mx1 = fmaxf(mx1, fmaxf(s[m][in][2], s[m][in][3]));
      }
      mx0 = fmaxf(mx0, __shfl_xor_sync(0xffffffffu, mx0, 1));
      mx0 = fmaxf(mx0, __shfl_xor_sync(0xffffffffu, mx0, 2));
      mx1 = fmaxf(mx1, __shfl_xor_sync(0xffffffffu, mx1, 1));
      mx1 = fmaxf(mx1, __shfl_xor_sync(0xffffffffu, mx1, 2));

      float mn0 = fmaxf(mo[2*m], mx0), mn1 = fmaxf(mo[2*m+1], mx1);
      float sc0 = exp2f(mo[2*m] - mn0), sc1 = exp2f(mo[2*m+1] - mn1);

      float rs0=0.f, rs1=0.f;
      #pragma unroll
      for(int in=0;in<8;in++){
        s[m][in][0] = exp2f(s[m][in][0]-mn0); rs0 += s[m][in][0];
        s[m][in][1] = exp2f(s[m][in][1]-mn0); rs0 += s[m][in][1];
        s[m][in][2] = exp2f(s[m][in][2]-mn1); rs1 += s[m][in][2];
        s[m][in][3] = exp2f(s[m][in][3]-mn1); rs1 += s[m][in][3];
      }
      rs0 += __shfl_xor_sync(0xffffffffu, rs0, 1);
      rs0 += __shfl_xor_sync(0xffffffffu, rs0, 2);
      rs1 += __shfl_xor_sync(0xffffffffu, rs1, 1);
      rs1 += __shfl_xor_sync(0xffffffffu, rs1, 2);

      lo[2*m]   = lo[2*m]*sc0 + rs0;
      lo[2*m+1] = lo[2*m+1]*sc1 + rs1;
      mo[2*m] = mn0; mo[2*m+1] = mn1;

      #pragma unroll
      for(int in=0;in<8;in++){
        o[m][in][0]*=sc0; o[m][in][1]*=sc0; o[m][in][2]*=sc1; o[m][in][3]*=sc1;
      }
    }

    #pragma unroll
    for(int kb=0;kb<4;kb++){
      uint32_t ap0[4], ap1[4];
      ap0[0] = h2u(__floats2half2_rn(s[0][2*kb  ][0], s[0][2*kb  ][1]));
      ap0[1] = h2u(__floats2half2_rn(s[0][2*kb  ][2], s[0][2*kb  ][3]));
      ap0[2] = h2u(__floats2half2_rn(s[0][2*kb+1][0], s[0][2*kb+1][1]));
      ap0[3] = h2u(__floats2half2_rn(s[0][2*kb+1][2], s[0][2*kb+1][3]));
      ap1[0] = h2u(__floats2half2_rn(s[1][2*kb  ][0], s[1][2*kb  ][1]));
      ap1[1] = h2u(__floats2half2_rn(s[1][2*kb  ][2], s[1][2*kb  ][3]));
      ap1[2] = h2u(__floats2half2_rn(s[1][2*kb+1][0], s[1][2*kb+1][1]));
      ap1[3] = h2u(__floats2half2_rn(s[1][2*kb+1][2], s[1][2*kb+1][3]));
      #pragma unroll
      for(int p=0;p<4;p++){
        uint32_t b0,b1,b2,b3;
        ldsm4(b0,b1,b2,b3, vab + p*PSTRIDE + kb*32);
        uint32_t bfa[2] = {b0,b1}, bfb[2] = {b2,b3};
        mma_f16(o[0][2*p  ], ap0, bfa);
        mma_f16(o[0][2*p+1], ap0, bfb);
        mma_f16(o[1][2*p  ], ap1, bfa);
        mma_f16(o[1][2*p+1], ap1, bfb);
      }
    }
    __syncthreads();
  }

  #pragma unroll
  for(int m=0;m<2;m++){
    float inv0 = 1.f/lo[2*m], inv1 = 1.f/lo[2*m+1];
    int r0 = q0 + rb + m*16 + g;
    __half* op0 = g_ctx16 + (size_t)(b*L_ + r0    )*D_ + (bh&7)*HD_;
    __half* op1 = g_ctx16 + (size_t)(b*L_ + r0 + 8)*D_ + (bh&7)*HD_;
    #pragma unroll
    for(int in=0;in<8;in++){
      int d = in*8 + tg*2;
      *(__half2*)(op0 + d) = __floats2half2_rn(o[m][in][0]*inv0, o[m][in][1]*inv0);
      *(__half2*)(op1 + d) = __floats2half2_rn(o[m][in][2]*inv1, o[m][in][3]*inv1);
    }
  }
}

// ---------------------------------------------------------------------------
extern "C" void kernel_launch(void* const* d_in, const int* in_sizes, int n_in,
                              void* d_out, int out_size)
{
  (void)in_sizes; (void)n_in; (void)out_size;
  const float* query = (const float*)d_in[0];
  const float* key   = (const float*)d_in[1];
  const float* value = (const float*)d_in[2];
  const int*   mask  = (const int*)d_in[3];
  const float* Wq = (const float*)d_in[4];
  const float* bq = (const float*)d_in[5];
  const float* Wk = (const float*)d_in[6];
  const float* bk = (const float*)d_in[7];
  const float* Wv = (const float*)d_in[8];
  const float* bv = (const float*)d_in[9];
  const float* Wo = (const float*)d_in[10];
  const float* bo = (const float*)d_in[11];
  float* out = (float*)d_out;

  static bool attr_done = false;
  if(!attr_done){
    cudaFuncSetAttribute(gemm_f16,   cudaFuncAttributeMaxDynamicSharedMemorySize, GEMM16_SMEM);
    cudaFuncSetAttribute(flash_attn, cudaFuncAttributeMaxDynamicSharedMemorySize, FLASH_SMEM);
    attr_done = true;
  }

  conv16<<<(int)(MD/4/256), 256>>>(query, key, value, Wq, Wk, Wv, Wo);

  dim3 gq(D_/GBN, M_/GBM, 3);       // (4, 64, 3) — QKV fused
  gemm_f16<<<gq, 256, GEMM16_SMEM>>>(bq, bk, bv, bo, nullptr, 1);

  dim3 fg(L_/FM, B_*H_);            // (16, 16)
  flash_attn<<<fg, 256, FLASH_SMEM>>>(mask);

  dim3 go(D_/GBN, M_/GBM, 1);       // (4, 64) — output projection
  gemm_f16<<<go, 256, GEMM16_SMEM>>>(bq, bk, bv, bo, out, 4);
}